// round 11
// baseline (speedup 1.0000x reference)
#include <cuda_runtime.h>
#include <cuda_bf16.h>
#include <cstdint>

// ---------------- problem constants ----------------
#define FH_   50
#define FW_   84
#define A_    12
#define B_    4
#define PIX   (FH_*FW_)        // 4200
#define N_ANCH (PIX*A_)        // 50400
#define PRE   6000
#define POST  300
#define NMS_THR 0.7f
#define NBUCK 4096
#define NBLK  197              // ceil(N_ANCH/256)
#define CAPA  4096             // fast-path compact capacity (top-2048 select)
#define FCAP  8192             // fallback compact capacity
#define INV30 0x3FFFFFFFu
// fast-path corner: top R1 rows x R1 cols
#define R1    2048
#define CH1   32               // R1/64 column words
#define RT1   8                // R1/256 row tiles
#define MROWS 256
#define NPAD  51200            // N_ANCH rounded up to 1024

static_assert(CH1*64 == R1 && RT1*MROWS == R1, "phase1 dims");
static_assert(NBLK*256 >= N_ANCH, "NBLK");
static_assert(N_ANCH < 65536, "index must fit in 16 bits");

// Correctly-rounded float exp: short fp64 poly + Ziv check, rare libdevice
// fallback. Bit-identical to (float)exp((double)x) for every input.
__device__ __forceinline__ float exp_cr(float x) {
    double xd = (double)x;
    double t  = xd * 1.4426950408889634;
    int    k  = __double2int_rn(t);
    double kd = (double)k;
    double r  = __fma_rn(kd, -0.6931471805599453,    xd);
    r         = __fma_rn(kd, -2.3190468138462996e-17, r);
    double p = 2.505210838544172e-08;
    p = __fma_rn(p, r, 2.755731922398589e-07);
    p = __fma_rn(p, r, 2.7557319223985893e-06);
    p = __fma_rn(p, r, 2.48015873015873e-05);
    p = __fma_rn(p, r, 1.984126984126984e-04);
    p = __fma_rn(p, r, 1.3888888888888889e-03);
    p = __fma_rn(p, r, 8.333333333333333e-03);
    p = __fma_rn(p, r, 4.1666666666666664e-02);
    p = __fma_rn(p, r, 0.16666666666666666);
    p = __fma_rn(p, r, 0.5);
    p = __fma_rn(p, r, 1.0);
    p = __fma_rn(p, r, 1.0);
    double yd = p * __longlong_as_double((long long)(1023 + k) << 52);
    float flo = (float)(yd * (1.0 - 1.0e-12));
    float fhi = (float)(yd * (1.0 + 1.0e-12));
    if (flo == fhi) return flo;
    return (float)exp(xd);
}

// ---------------- static device scratch ----------------
__device__ float4             g_boxes[B_*N_ANCH];
__device__ unsigned int       g_code [B_*N_ANCH];
__device__ int                g_hist [B_*NBUCK];   // zero-init; re-zeroed by cutoff
__device__ int                g_cutA [B_];
__device__ int                g_cutB [B_];
__device__ int                g_bcnt [B_*NBLK];
__device__ int                g_boff [B_*NBLK];
__device__ int                g_ovf  [B_];
__device__ unsigned long long g_ckeys[B_*CAPA];
__device__ int                g_cidx [B_*CAPA];
__device__ float4             g_sboxes[B_*R1];
__device__ float              g_sarea [B_*R1];
__device__ unsigned char      g_svalid[B_*R1];
// corner mask (zero-init; fully-lower words never written -> stay 0)
__device__ unsigned long long g_mask1[(size_t)B_*R1*CH1];
// fallback scratch (never touched on fast path)
__device__ unsigned long long g_fkeys[B_*FCAP];

// ---------------- kernel 1: softmax + decode + code + histogram ----------------
__global__ void prep_kernel(const float* __restrict__ scores,
                            const float* __restrict__ deltas,
                            const float* __restrict__ anchors,
                            const float* __restrict__ iminfo)
{
    int idx = blockIdx.x * blockDim.x + threadIdx.x;
    if (idx >= B_*N_ANCH) return;
    int pix = idx % PIX;
    int ba  = idx / PIX;
    int b   = ba / A_;
    int a   = ba % A_;

    // softmax over (2a,2a+1): max-shift makes one exp exactly 1.0; single
    // E=exp(-|s1-s0|) reproduces the reference bitwise.
    const float* sp = scores + ((size_t)(b*2*A_ + 2*a))*PIX + pix;
    float s0 = sp[0];
    float s1 = sp[PIX];
    float dneg = (s1 >= s0) ? __fsub_rn(s0, s1) : __fsub_rn(s1, s0);
    float E     = exp_cr(dneg);
    float denom = __fadd_rn(E, 1.0f);
    float p = (s1 >= s0) ? __fdiv_rn(1.0f, denom) : __fdiv_rn(E, denom);

    const float* dp = deltas + ((size_t)(b*4*A_ + 4*a))*PIX + pix;
    float d0 = dp[0], d1 = dp[PIX], d2 = dp[2*PIX], d3 = dp[3*PIX];

    int i = pix*A_ + a;
    float4 an = reinterpret_cast<const float4*>(anchors)[i];

    float w  = an.z - an.x + 1.0f;
    float h  = an.w - an.y + 1.0f;
    float cx = __fadd_rn(an.x, __fmul_rn(0.5f, w));
    float cy = __fadd_rn(an.y, __fmul_rn(0.5f, h));
    float pcx = __fadd_rn(__fmul_rn(d0, w), cx);
    float pcy = __fadd_rn(__fmul_rn(d1, h), cy);
    float pw  = __fmul_rn(exp_cr(d2), w);
    float ph  = __fmul_rn(exp_cr(d3), h);
    float hx  = __fmul_rn(0.5f, pw);
    float hy  = __fmul_rn(0.5f, ph);
    float x1  = __fsub_rn(pcx, hx);
    float y1  = __fsub_rn(pcy, hy);
    float x2  = __fadd_rn(pcx, hx);
    float y2  = __fadd_rn(pcy, hy);

    float imh = iminfo[b*4+0], imw = iminfo[b*4+1];
    float sh  = iminfo[b*4+2], sw  = iminfo[b*4+3];
    float mw  = imw - 1.0f, mh = imh - 1.0f;
    x1 = fminf(fmaxf(x1, 0.0f), mw);
    y1 = fminf(fmaxf(y1, 0.0f), mh);
    x2 = fminf(fmaxf(x2, 0.0f), mw);
    y2 = fminf(fmaxf(y2, 0.0f), mh);

    float ws = x2 - x1 + 1.0f;
    float hs = y2 - y1 + 1.0f;
    bool valid = (ws >= __fmul_rn(16.0f, sw)) && (hs >= __fmul_rn(16.0f, sh));

    unsigned int code = valid ? (0x3F800000u - __float_as_uint(p)) : INV30;

    int gi = b*N_ANCH + i;
    g_code [gi] = code;
    g_boxes[gi] = make_float4(x1, y1, x2, y2);
    atomicAdd(&g_hist[b*NBUCK + (code >> 18)], 1);
}

// ---------------- kernel 2: cutoffs at rank R1 / rank PRE + hist re-zero ------
__global__ void cutoff_kernel()
{
    int b = blockIdx.x;
    int lane = threadIdx.x;                  // 32 threads
    const unsigned FULL = 0xFFFFFFFFu;
    int running = 0;
    int cutA = NBUCK - 1, cutB = NBUCK - 1;
    bool fA = false, fB = false;
    for (int it = 0; it < NBUCK/32; it++) {
        int v = g_hist[b*NBUCK + it*32 + lane];
        int s = v;
        #pragma unroll
        for (int d = 1; d < 32; d <<= 1) {
            int t = __shfl_up_sync(FULL, s, d);
            if (lane >= d) s += t;
        }
        int cum = running + s;
        if (!fA) {
            unsigned mm = __ballot_sync(FULL, cum >= R1);
            if (mm) { cutA = it*32 + __ffs(mm) - 1; fA = true; }
        }
        if (!fB) {
            unsigned mm = __ballot_sync(FULL, cum >= PRE);
            if (mm) { cutB = it*32 + __ffs(mm) - 1; fB = true; }
        }
        if (fA && fB) break;
        running += __shfl_sync(FULL, s, 31);
    }
    if (lane == 0) { g_cutA[b] = cutA; g_cutB[b] = cutB; }
    // re-zero the full histogram for the next graph replay (sole reader is us)
    for (int j = lane; j < NBUCK; j += 32) g_hist[b*NBUCK + j] = 0;
}

// ---------------- kernel 3: per-block predicate counts ----------------
__global__ void count_kernel()
{
    int blk = blockIdx.x, b = blockIdx.y;
    int i = blk*256 + threadIdx.x;
    int cutA = g_cutA[b];
    bool pred = (i < N_ANCH) && ((int)(g_code[b*N_ANCH + i] >> 18) <= cutA);
    int cnt = __syncthreads_count(pred);
    if (threadIdx.x == 0) g_bcnt[b*NBLK + blk] = cnt;
}

// ---------------- kernel 4: scan block counts + sentinel fill + ovf ----------------
__global__ void bscan_kernel()
{
    int b = blockIdx.x;
    int tid = threadIdx.x;                  // 256 threads
    __shared__ int sc[256];
    int v = (tid < NBLK) ? g_bcnt[b*NBLK + tid] : 0;
    sc[tid] = v;
    __syncthreads();
    for (int off = 1; off < 256; off <<= 1) {
        int t2 = (tid >= off) ? sc[tid - off] : 0;
        __syncthreads();
        sc[tid] += t2;
        __syncthreads();
    }
    if (tid < NBLK) g_boff[b*NBLK + tid] = sc[tid] - v;   // exclusive
    if (tid == 255) g_ovf[b] = (sc[255] > CAPA) ? 1 : 0;
    // sentinel-fill compact buffer (scatter runs in a later kernel)
    for (int j = tid; j < CAPA; j += 256) g_ckeys[b*CAPA + j] = ~0ull;
}

// ---------------- kernel 5: stable scatter of selected items ----------------
__global__ void scatter_kernel()
{
    int blk = blockIdx.x, b = blockIdx.y;
    int tid = threadIdx.x;                  // 256 threads
    int wid = tid >> 5, lane = tid & 31;
    const unsigned FULL = 0xFFFFFFFFu;
    __shared__ int wcnt[8];

    int i = blk*256 + tid;
    unsigned code = (i < N_ANCH) ? g_code[b*N_ANCH + i] : INV30;
    int cutA = g_cutA[b];
    bool pred = (i < N_ANCH) && ((int)(code >> 18) <= cutA);
    unsigned mm = __ballot_sync(FULL, pred);
    int pre = __popc(mm & ((1u << lane) - 1u));
    if (lane == 0) wcnt[wid] = __popc(mm);
    __syncthreads();
    if (tid == 0) {
        int ex = 0;
        #pragma unroll
        for (int w = 0; w < 8; w++) { int t = wcnt[w]; wcnt[w] = ex; ex += t; }
    }
    __syncthreads();
    if (pred) {
        int pos = g_boff[b*NBLK + blk] + wcnt[wid] + pre;
        if (pos < CAPA) {
            // key: 30-bit code | 16-bit stable compact position (index order)
            g_ckeys[b*CAPA + pos] = ((unsigned long long)code << 16) | (unsigned)pos;
            g_cidx [b*CAPA + pos] = i;
        }
    }
}

// ---------------- kernel 6: one-CTA bitonic sort of 4096 keys + gather --------
__global__ void __launch_bounds__(1024) sort_kernel()
{
    __shared__ unsigned long long sk[CAPA];   // 32 KB
    int b = blockIdx.x;
    int tid = threadIdx.x;                    // 1024 threads

    for (int i = tid; i < CAPA; i += 1024) sk[i] = g_ckeys[b*CAPA + i];
    __syncthreads();

    // bitonic sort, ascending; keys are unique (code|pos) -> exact total order.
    // sentinel ~0ull compares above every valid key.
    for (int k = 2; k <= CAPA; k <<= 1) {
        for (int j = k >> 1; j > 0; j >>= 1) {
            for (int i = tid; i < CAPA; i += 1024) {
                int ixj = i ^ j;
                if (ixj > i) {
                    bool up = ((i & k) == 0);
                    unsigned long long a = sk[i], c = sk[ixj];
                    if ((a > c) == up) { sk[i] = c; sk[ixj] = a; }
                }
            }
            __syncthreads();
        }
    }

    // gather top-R1 boxes/areas/valid
    for (int r = tid; r < R1; r += 1024) {
        unsigned long long key = sk[r];
        unsigned pos  = (unsigned)(key & 0xFFFFu);
        unsigned code = (unsigned)((key >> 16) & 0x3FFFFFFFull);
        bool ok = (pos < CAPA);
        float4 bx = make_float4(0.f, 0.f, 0.f, 0.f);
        float  ar = 0.f;
        if (ok) {
            int idx = g_cidx[b*CAPA + pos];
            bx = g_boxes[b*N_ANCH + idx];
            ar = (bx.z - bx.x + 1.0f) * (bx.w - bx.y + 1.0f);
        }
        g_sboxes[b*R1 + r] = bx;
        g_sarea [b*R1 + r] = ar;
        g_svalid[b*R1 + r] = (ok && code != INV30) ? 1 : 0;
    }
}

// ---------------- shared IoU bit computation ----------------
__device__ __forceinline__ unsigned long long iou_bits(
    float4 bi, float ai, const float4* cbox, const float* carea, int jmax)
{
    unsigned long long bits = 0ull;
    #pragma unroll 8
    for (int k = 0; k < jmax; k++) {
        float4 bj = cbox[k];
        float xx1 = fmaxf(bi.x, bj.x);
        float yy1 = fmaxf(bi.y, bj.y);
        float xx2 = fminf(bi.z, bj.z);
        float yy2 = fminf(bi.w, bj.w);
        float iw = fmaxf(xx2 - xx1 + 1.0f, 0.0f);
        float ih = fmaxf(yy2 - yy1 + 1.0f, 0.0f);
        float inter = __fmul_rn(iw, ih);
        float sum   = __fadd_rn(ai, carea[k]);
        // exact prefilter: iou>0.7 requires inter>0.41*sum; 4*inter>=sum is a
        // safe necessary condition -> kept-bit set is bit-identical
        if (__fmul_rn(inter, 4.0f) >= sum) {
            float uni = __fsub_rn(sum, inter);
            float iou = __fdiv_rn(inter, uni);
            if (iou > NMS_THR) bits |= (1ull << k);
        }
    }
    return bits;
}

// ---------------- kernel 7: corner mask (top R1 x R1) ----------------
__global__ void mask1_kernel()
{
    int cb = blockIdx.x;                    // column word, < CH1
    int rt = blockIdx.y;                    // row 256-tile, < RT1
    int b  = blockIdx.z;
    int j0 = cb * 64;
    if (j0 + 63 < rt * MROWS) return;       // fully-lower tile: words stay 0

    __shared__ float4 cbox[64];
    __shared__ float  carea[64];
    int t = threadIdx.x;
    if (t < 64) {
        cbox[t]  = g_sboxes[b*R1 + j0 + t];
        carea[t] = g_sarea [b*R1 + j0 + t];
    }
    __syncthreads();

    int i = rt * MROWS + t;                 // < R1
    int d = i - j0;
    size_t word = ((size_t)(b*R1 + i))*CH1 + cb;
    if (d >= 63) { g_mask1[word] = 0ull; return; }

    unsigned long long bits = iou_bits(g_sboxes[b*R1 + i], g_sarea[b*R1 + i],
                                       cbox, carea, 64);
    if (d >= 0) bits &= (~0ull) << (d + 1);
    g_mask1[word] = bits;
}

// ---------------- kernel 8: corner scan + inline exact fallback ----------------
__global__ void __launch_bounds__(1024) scan1_fb_kernel(float* __restrict__ out)
{
    int b    = blockIdx.x;
    int tid  = threadIdx.x;                 // 1024 threads
    int lane = tid & 31;
    int warp = tid >> 5;
    const unsigned FULL = 0xFFFFFFFFu;

    __shared__ unsigned long long removed[CH1];
    __shared__ int keptList[POST];
    __shared__ int sDone;

    // ---- warp 0: greedy scan over the corner mask ----
    if (warp == 0) {
        if (lane < CH1) removed[lane] = 0ull;
        __syncwarp();

        int kept = 0;
        for (int c = 0; c < CH1 && kept < POST; c++) {
            int r0 = c * 64;
            int ra = r0 + lane, rb2 = r0 + 32 + lane;

            unsigned lo = __ballot_sync(FULL, g_svalid[b*R1 + ra ] != 0);
            unsigned hi = __ballot_sync(FULL, g_svalid[b*R1 + rb2] != 0);
            unsigned long long validm = (unsigned long long)lo | ((unsigned long long)hi << 32);

            unsigned long long m0 = g_mask1[((size_t)(b*R1 + ra ))*CH1 + c];
            unsigned long long m1 = g_mask1[((size_t)(b*R1 + rb2))*CH1 + c];

            unsigned long long cand = validm & ~removed[c];
            unsigned long long keptbits = 0ull;
            while (cand && kept < POST) {
                int l = __ffsll((long long)cand) - 1;
                keptList[kept] = r0 + l;
                kept++;
                keptbits |= (1ull << l);
                unsigned long long intra = (l < 32) ? __shfl_sync(FULL, m0, l)
                                                    : __shfl_sync(FULL, m1, l - 32);
                cand &= ~intra;
                cand &= ~(1ull << l);
            }

            if (keptbits) {
                unsigned long long acc = 0ull;       // lane -> word (CH1==32)
                unsigned long long kb2 = keptbits;
                while (kb2) {
                    int l = __ffsll((long long)kb2) - 1;
                    kb2 &= kb2 - 1;
                    acc |= g_mask1[((size_t)(b*R1 + r0 + l))*CH1 + lane];
                }
                removed[lane] |= acc;
            }
            __syncwarp();
        }
        if (lane == 0)
            sDone = (kept >= POST && g_ovf[b] == 0) ? 1 : 0;
    }
    __syncthreads();

    if (sDone) {
        for (int r = tid; r < POST; r += 1024) {
            float* o = out + ((size_t)(b*POST + r))*5;
            float4 bx = g_sboxes[b*R1 + keptList[r]];
            o[0] = (float)b; o[1] = bx.x; o[2] = bx.y; o[3] = bx.z; o[4] = bx.w;
        }
        return;
    }

    // ================= exact fallback (not expected on real data) ============
    __shared__ int fCnt;
    if (tid == 0) fCnt = 0;
    __syncthreads();

    int cutB = g_cutB[b];
    for (int i0 = 0; i0 < NPAD; i0 += 1024) {
        int i = i0 + tid;
        unsigned code = (i < N_ANCH) ? g_code[b*N_ANCH + i] : 0xFFFFFFFFu;
        bool pred = (i < N_ANCH) && ((int)(code >> 18) <= cutB);
        unsigned mm = __ballot_sync(FULL, pred);
        int pre = __popc(mm & ((1u << lane) - 1u));
        int wbase = 0;
        if (lane == 0 && mm) wbase = atomicAdd(&fCnt, __popc(mm));
        wbase = __shfl_sync(FULL, wbase, 0);
        if (pred) {
            int pos = wbase + pre;
            if (pos < FCAP)
                g_fkeys[b*FCAP + pos] = ((unsigned long long)code << 16) | (unsigned)i;
        }
    }
    __syncthreads();
    int total = fCnt;
    for (int j = tid; j < FCAP; j += 1024)
        if (j >= total) g_fkeys[b*FCAP + j] = ~0ull;
    __syncthreads();

    // bitonic sort of FCAP keys in gmem (single CTA; perf irrelevant)
    unsigned long long* Ak = &g_fkeys[b*FCAP];
    for (int k = 2; k <= FCAP; k <<= 1) {
        for (int j = k >> 1; j > 0; j >>= 1) {
            for (int i = tid; i < FCAP; i += 1024) {
                int ixj = i ^ j;
                if (ixj > i) {
                    bool up = ((i & k) == 0);
                    unsigned long long a = Ak[i], c = Ak[ixj];
                    if ((a > c) == up) { Ak[i] = c; Ak[ixj] = a; }
                }
            }
            __syncthreads();
        }
    }

    // greedy NMS over sorted top-PRE with exact IoU semantics
    __shared__ float4 kbox[POST];
    __shared__ float  karea[POST];
    __shared__ int kcnt, supp;
    if (tid == 0) kcnt = 0;
    __syncthreads();

    for (int r = 0; r < PRE; r++) {
        if (kcnt >= POST) break;
        unsigned long long key = Ak[r];
        unsigned code = (unsigned)((key >> 16) & 0x3FFFFFFFull);
        if (code == INV30) break;           // sorted: rest invalid/sentinel
        int idx = (int)(key & 0xFFFFull);
        float4 bx = g_boxes[b*N_ANCH + idx];
        float ar = (bx.z - bx.x + 1.0f) * (bx.w - bx.y + 1.0f);
        if (tid == 0) supp = 0;
        __syncthreads();
        int kc = kcnt;
        for (int t = tid; t < kc; t += 1024) {
            float4 bj = kbox[t];
            float xx1 = fmaxf(bx.x, bj.x);
            float yy1 = fmaxf(bx.y, bj.y);
            float xx2 = fminf(bx.z, bj.z);
            float yy2 = fminf(bx.w, bj.w);
            float iw = fmaxf(xx2 - xx1 + 1.0f, 0.0f);
            float ih = fmaxf(yy2 - yy1 + 1.0f, 0.0f);
            float inter = __fmul_rn(iw, ih);
            float sum   = __fadd_rn(ar, karea[t]);
            if (__fmul_rn(inter, 4.0f) >= sum) {
                float uni = __fsub_rn(sum, inter);
                float iou = __fdiv_rn(inter, uni);
                if (iou > NMS_THR) supp = 1;
            }
        }
        __syncthreads();
        if (!supp && tid == 0) { kbox[kcnt] = bx; karea[kcnt] = ar; kcnt = kcnt + 1; }
        __syncthreads();
    }

    int kc = kcnt;
    for (int r = tid; r < POST; r += 1024) {
        float* o = out + ((size_t)(b*POST + r))*5;
        if (r < kc) {
            float4 bx = kbox[r];
            o[0] = (float)b; o[1] = bx.x; o[2] = bx.y; o[3] = bx.z; o[4] = bx.w;
        } else {
            o[0] = (float)b; o[1] = 0.0f; o[2] = 0.0f; o[3] = 0.0f; o[4] = 0.0f;
        }
    }
}

// ---------------- launch: 8 kernels, no memset ----------------
extern "C" void kernel_launch(void* const* d_in, const int* in_sizes, int n_in,
                              void* d_out, int out_size)
{
    const float* scores  = (const float*)d_in[0];
    const float* deltas  = (const float*)d_in[1];
    const float* anchors = (const float*)d_in[2];
    const float* iminfo  = (const float*)d_in[3];
    float* out = (float*)d_out;

    const int total = B_ * N_ANCH;
    prep_kernel<<<(total + 255) / 256, 256>>>(scores, deltas, anchors, iminfo);
    cutoff_kernel<<<B_, 32>>>();
    count_kernel<<<dim3(NBLK, B_), 256>>>();
    bscan_kernel<<<B_, 256>>>();
    scatter_kernel<<<dim3(NBLK, B_), 256>>>();
    sort_kernel<<<B_, 1024>>>();

    dim3 m1grid(CH1, RT1, B_);
    mask1_kernel<<<m1grid, MROWS>>>();
    scan1_fb_kernel<<<B_, 1024>>>(out);
}

// round 12
// speedup vs baseline: 1.0571x; 1.0571x over previous
#include <cuda_runtime.h>
#include <cuda_bf16.h>
#include <cub/cub.cuh>
#include <cstdint>

// ---------------- problem constants ----------------
#define FH_   50
#define FW_   84
#define A_    12
#define B_    4
#define PIX   (FH_*FW_)        // 4200
#define N_ANCH (PIX*A_)        // 50400
#define PRE   6000
#define POST  300
#define NMS_THR 0.7f
#define NBUCK 4096
#define NBLK  197              // ceil(N_ANCH/256)
#define CAPA  4096             // fast-path compact capacity (top-2048 select)
#define FCAP  8192             // fallback compact capacity
#define INV30 0x3FFFFFFFu
// fast-path corner: top R1 rows x R1 cols
#define R1    2048
#define CH1   32               // R1/64 column words
#define RT1   8                // R1/256 row tiles
#define MROWS 256
#define NPAD  51200            // N_ANCH rounded up to 1024

static_assert(CH1*64 == R1 && RT1*MROWS == R1, "phase1 dims");
static_assert(NBLK*256 >= N_ANCH, "NBLK");
static_assert(N_ANCH < 65536, "index must fit in 16 bits");

// Correctly-rounded float exp: short fp64 poly + Ziv check, rare libdevice
// fallback. Bit-identical to (float)exp((double)x) for every input.
__device__ __forceinline__ float exp_cr(float x) {
    double xd = (double)x;
    double t  = xd * 1.4426950408889634;
    int    k  = __double2int_rn(t);
    double kd = (double)k;
    double r  = __fma_rn(kd, -0.6931471805599453,    xd);
    r         = __fma_rn(kd, -2.3190468138462996e-17, r);
    double p = 2.505210838544172e-08;
    p = __fma_rn(p, r, 2.755731922398589e-07);
    p = __fma_rn(p, r, 2.7557319223985893e-06);
    p = __fma_rn(p, r, 2.48015873015873e-05);
    p = __fma_rn(p, r, 1.984126984126984e-04);
    p = __fma_rn(p, r, 1.3888888888888889e-03);
    p = __fma_rn(p, r, 8.333333333333333e-03);
    p = __fma_rn(p, r, 4.1666666666666664e-02);
    p = __fma_rn(p, r, 0.16666666666666666);
    p = __fma_rn(p, r, 0.5);
    p = __fma_rn(p, r, 1.0);
    p = __fma_rn(p, r, 1.0);
    double yd = p * __longlong_as_double((long long)(1023 + k) << 52);
    float flo = (float)(yd * (1.0 - 1.0e-12));
    float fhi = (float)(yd * (1.0 + 1.0e-12));
    if (flo == fhi) return flo;
    return (float)exp(xd);
}

// ---------------- static device scratch ----------------
__device__ float4             g_boxes[B_*N_ANCH];
__device__ unsigned int       g_code [B_*N_ANCH];
__device__ int                g_hist [B_*NBUCK];   // zero-init; re-zeroed by cutoff
__device__ int                g_cutA [B_];
__device__ int                g_cutB [B_];
__device__ int                g_cnt  [B_];         // compaction counter (zeroed by cutoff)
__device__ unsigned long long g_ckeys[B_*CAPA];    // sentinel-filled by prep
__device__ float4             g_sboxes[B_*R1];
__device__ float              g_sarea [B_*R1];
__device__ unsigned char      g_svalid[B_*R1];
// corner mask (zero-init; fully-lower words never written -> stay 0)
__device__ unsigned long long g_mask1[(size_t)B_*R1*CH1];
// fallback scratch (never touched on fast path)
__device__ unsigned long long g_fkeys[B_*FCAP];

// ---------------- kernel 1: softmax + decode + code + histogram + sentinel ----
__global__ void prep_kernel(const float* __restrict__ scores,
                            const float* __restrict__ deltas,
                            const float* __restrict__ anchors,
                            const float* __restrict__ iminfo)
{
    int idx = blockIdx.x * blockDim.x + threadIdx.x;
    if (idx >= B_*N_ANCH) return;

    // spare duty: sentinel-fill compact buffer for this replay
    if (idx < B_*CAPA) g_ckeys[idx] = ~0ull;

    int pix = idx % PIX;
    int ba  = idx / PIX;
    int b   = ba / A_;
    int a   = ba % A_;

    // softmax over (2a,2a+1): max-shift makes one exp exactly 1.0; single
    // E=exp(-|s1-s0|) reproduces the reference bitwise.
    const float* sp = scores + ((size_t)(b*2*A_ + 2*a))*PIX + pix;
    float s0 = sp[0];
    float s1 = sp[PIX];
    float dneg = (s1 >= s0) ? __fsub_rn(s0, s1) : __fsub_rn(s1, s0);
    float E     = exp_cr(dneg);
    float denom = __fadd_rn(E, 1.0f);
    float p = (s1 >= s0) ? __fdiv_rn(1.0f, denom) : __fdiv_rn(E, denom);

    const float* dp = deltas + ((size_t)(b*4*A_ + 4*a))*PIX + pix;
    float d0 = dp[0], d1 = dp[PIX], d2 = dp[2*PIX], d3 = dp[3*PIX];

    int i = pix*A_ + a;
    float4 an = reinterpret_cast<const float4*>(anchors)[i];

    float w  = an.z - an.x + 1.0f;
    float h  = an.w - an.y + 1.0f;
    float cx = __fadd_rn(an.x, __fmul_rn(0.5f, w));
    float cy = __fadd_rn(an.y, __fmul_rn(0.5f, h));
    float pcx = __fadd_rn(__fmul_rn(d0, w), cx);
    float pcy = __fadd_rn(__fmul_rn(d1, h), cy);
    float pw  = __fmul_rn(exp_cr(d2), w);
    float ph  = __fmul_rn(exp_cr(d3), h);
    float hx  = __fmul_rn(0.5f, pw);
    float hy  = __fmul_rn(0.5f, ph);
    float x1  = __fsub_rn(pcx, hx);
    float y1  = __fsub_rn(pcy, hy);
    float x2  = __fadd_rn(pcx, hx);
    float y2  = __fadd_rn(pcy, hy);

    float imh = iminfo[b*4+0], imw = iminfo[b*4+1];
    float sh  = iminfo[b*4+2], sw  = iminfo[b*4+3];
    float mw  = imw - 1.0f, mh = imh - 1.0f;
    x1 = fminf(fmaxf(x1, 0.0f), mw);
    y1 = fminf(fmaxf(y1, 0.0f), mh);
    x2 = fminf(fmaxf(x2, 0.0f), mw);
    y2 = fminf(fmaxf(y2, 0.0f), mh);

    float ws = x2 - x1 + 1.0f;
    float hs = y2 - y1 + 1.0f;
    bool valid = (ws >= __fmul_rn(16.0f, sw)) && (hs >= __fmul_rn(16.0f, sh));

    unsigned int code = valid ? (0x3F800000u - __float_as_uint(p)) : INV30;

    int gi = b*N_ANCH + i;
    g_code [gi] = code;
    g_boxes[gi] = make_float4(x1, y1, x2, y2);
    atomicAdd(&g_hist[b*NBUCK + (code >> 18)], 1);
}

// ---------------- kernel 2: cutoffs + hist re-zero + counter zero -------------
__global__ void cutoff_kernel()
{
    int b = blockIdx.x;
    int lane = threadIdx.x;                  // 32 threads
    const unsigned FULL = 0xFFFFFFFFu;
    int running = 0;
    int cutA = NBUCK - 1, cutB = NBUCK - 1;
    bool fA = false, fB = false;
    for (int it = 0; it < NBUCK/32; it++) {
        int v = g_hist[b*NBUCK + it*32 + lane];
        int s = v;
        #pragma unroll
        for (int d = 1; d < 32; d <<= 1) {
            int t = __shfl_up_sync(FULL, s, d);
            if (lane >= d) s += t;
        }
        int cum = running + s;
        if (!fA) {
            unsigned mm = __ballot_sync(FULL, cum >= R1);
            if (mm) { cutA = it*32 + __ffs(mm) - 1; fA = true; }
        }
        if (!fB) {
            unsigned mm = __ballot_sync(FULL, cum >= PRE);
            if (mm) { cutB = it*32 + __ffs(mm) - 1; fB = true; }
        }
        if (fA && fB) break;
        running += __shfl_sync(FULL, s, 31);
    }
    if (lane == 0) { g_cutA[b] = cutA; g_cutB[b] = cutB; g_cnt[b] = 0; }
    // re-zero the full histogram for the next graph replay (sole reader is us)
    for (int j = lane; j < NBUCK; j += 32) g_hist[b*NBUCK + j] = 0;
}

// ---------------- kernel 3: unordered warp-aggregated compaction --------------
// Order is irrelevant: key = (code<<16 | anchor_index) carries the exact
// (score, index) sort order, so any permutation sorts to the same sequence.
__global__ void compact_kernel()
{
    int blk = blockIdx.x, b = blockIdx.y;
    int tid = threadIdx.x;                  // 256 threads
    int lane = tid & 31;
    const unsigned FULL = 0xFFFFFFFFu;

    int i = blk*256 + tid;
    unsigned code = (i < N_ANCH) ? g_code[b*N_ANCH + i] : 0xFFFFFFFFu;
    int cutA = g_cutA[b];
    bool pred = (i < N_ANCH) && ((int)(code >> 18) <= cutA);
    unsigned mm = __ballot_sync(FULL, pred);
    int pre = __popc(mm & ((1u << lane) - 1u));
    int wbase = 0;
    if (lane == 0 && mm) wbase = atomicAdd(&g_cnt[b], __popc(mm));
    wbase = __shfl_sync(FULL, wbase, 0);
    if (pred) {
        int pos = wbase + pre;
        if (pos < CAPA)
            g_ckeys[b*CAPA + pos] = ((unsigned long long)code << 16) | (unsigned)i;
    }
}

// ---------------- kernel 4: one-CTA BlockRadixSort of 4096 keys + gather ------
__global__ void __launch_bounds__(1024) sort_kernel()
{
    int b = blockIdx.x;
    int tid = threadIdx.x;                  // 1024 threads
    typedef cub::BlockRadixSort<unsigned long long, 1024, 4> BRS;
    __shared__ typename BRS::TempStorage ts;

    unsigned long long keys[4];
    #pragma unroll
    for (int k = 0; k < 4; k++) keys[k] = g_ckeys[b*CAPA + tid*4 + k];
    BRS(ts).Sort(keys, 0, 46);              // 46-bit (code|index): exact order

    #pragma unroll
    for (int k = 0; k < 4; k++) {
        int r = tid*4 + k;
        if (r >= R1) break;
        unsigned long long key = keys[k];
        unsigned code = (unsigned)((key >> 16) & 0x3FFFFFFFull);
        bool ok = (code != INV30) && (key != ~0ull);
        float4 bx = make_float4(0.f, 0.f, 0.f, 0.f);
        float  ar = 0.f;
        if (key != ~0ull) {                 // real entry (possibly invalid-code)
            int idx = (int)(key & 0xFFFFull);
            bx = g_boxes[b*N_ANCH + idx];
            ar = (bx.z - bx.x + 1.0f) * (bx.w - bx.y + 1.0f);
        }
        g_sboxes[b*R1 + r] = bx;
        g_sarea [b*R1 + r] = ar;
        g_svalid[b*R1 + r] = ok ? 1 : 0;
    }
}

// ---------------- shared IoU bit computation ----------------
__device__ __forceinline__ unsigned long long iou_bits(
    float4 bi, float ai, const float4* cbox, const float* carea, int jmax)
{
    unsigned long long bits = 0ull;
    #pragma unroll 8
    for (int k = 0; k < jmax; k++) {
        float4 bj = cbox[k];
        float xx1 = fmaxf(bi.x, bj.x);
        float yy1 = fmaxf(bi.y, bj.y);
        float xx2 = fminf(bi.z, bj.z);
        float yy2 = fminf(bi.w, bj.w);
        float iw = fmaxf(xx2 - xx1 + 1.0f, 0.0f);
        float ih = fmaxf(yy2 - yy1 + 1.0f, 0.0f);
        float inter = __fmul_rn(iw, ih);
        float sum   = __fadd_rn(ai, carea[k]);
        // exact prefilter: iou>0.7 requires inter>0.41*sum; 4*inter>=sum is a
        // safe necessary condition -> kept-bit set is bit-identical
        if (__fmul_rn(inter, 4.0f) >= sum) {
            float uni = __fsub_rn(sum, inter);
            float iou = __fdiv_rn(inter, uni);
            if (iou > NMS_THR) bits |= (1ull << k);
        }
    }
    return bits;
}

// ---------------- kernel 5: corner mask (top R1 x R1) ----------------
__global__ void mask1_kernel()
{
    int cb = blockIdx.x;                    // column word, < CH1
    int rt = blockIdx.y;                    // row 256-tile, < RT1
    int b  = blockIdx.z;
    int j0 = cb * 64;
    if (j0 + 63 < rt * MROWS) return;       // fully-lower tile: words stay 0

    __shared__ float4 cbox[64];
    __shared__ float  carea[64];
    int t = threadIdx.x;
    if (t < 64) {
        cbox[t]  = g_sboxes[b*R1 + j0 + t];
        carea[t] = g_sarea [b*R1 + j0 + t];
    }
    __syncthreads();

    int i = rt * MROWS + t;                 // < R1
    int d = i - j0;
    size_t word = ((size_t)(b*R1 + i))*CH1 + cb;
    if (d >= 63) { g_mask1[word] = 0ull; return; }

    unsigned long long bits = iou_bits(g_sboxes[b*R1 + i], g_sarea[b*R1 + i],
                                       cbox, carea, 64);
    if (d >= 0) bits &= (~0ull) << (d + 1);
    g_mask1[word] = bits;
}

// ---------------- kernel 6: corner scan + inline exact fallback ----------------
__global__ void __launch_bounds__(1024) scan1_fb_kernel(float* __restrict__ out)
{
    int b    = blockIdx.x;
    int tid  = threadIdx.x;                 // 1024 threads
    int lane = tid & 31;
    int warp = tid >> 5;
    const unsigned FULL = 0xFFFFFFFFu;

    __shared__ unsigned long long removed[CH1];
    __shared__ int keptList[POST];
    __shared__ int sDone;

    // ---- warp 0: greedy scan over the corner mask ----
    if (warp == 0) {
        if (lane < CH1) removed[lane] = 0ull;
        __syncwarp();

        int kept = 0;
        for (int c = 0; c < CH1 && kept < POST; c++) {
            int r0 = c * 64;
            int ra = r0 + lane, rb2 = r0 + 32 + lane;

            unsigned lo = __ballot_sync(FULL, g_svalid[b*R1 + ra ] != 0);
            unsigned hi = __ballot_sync(FULL, g_svalid[b*R1 + rb2] != 0);
            unsigned long long validm = (unsigned long long)lo | ((unsigned long long)hi << 32);

            unsigned long long m0 = g_mask1[((size_t)(b*R1 + ra ))*CH1 + c];
            unsigned long long m1 = g_mask1[((size_t)(b*R1 + rb2))*CH1 + c];

            unsigned long long cand = validm & ~removed[c];
            unsigned long long keptbits = 0ull;
            while (cand && kept < POST) {
                int l = __ffsll((long long)cand) - 1;
                keptList[kept] = r0 + l;
                kept++;
                keptbits |= (1ull << l);
                unsigned long long intra = (l < 32) ? __shfl_sync(FULL, m0, l)
                                                    : __shfl_sync(FULL, m1, l - 32);
                cand &= ~intra;
                cand &= ~(1ull << l);
            }

            if (keptbits) {
                unsigned long long acc = 0ull;       // lane -> word (CH1==32)
                unsigned long long kb2 = keptbits;
                while (kb2) {
                    int l = __ffsll((long long)kb2) - 1;
                    kb2 &= kb2 - 1;
                    acc |= g_mask1[((size_t)(b*R1 + r0 + l))*CH1 + lane];
                }
                removed[lane] |= acc;
            }
            __syncwarp();
        }
        if (lane == 0)
            sDone = (kept >= POST && g_cnt[b] <= CAPA) ? 1 : 0;
    }
    __syncthreads();

    if (sDone) {
        for (int r = tid; r < POST; r += 1024) {
            float* o = out + ((size_t)(b*POST + r))*5;
            float4 bx = g_sboxes[b*R1 + keptList[r]];
            o[0] = (float)b; o[1] = bx.x; o[2] = bx.y; o[3] = bx.z; o[4] = bx.w;
        }
        return;
    }

    // ================= exact fallback (not expected on real data) ============
    __shared__ int fCnt;
    if (tid == 0) fCnt = 0;
    __syncthreads();

    int cutB = g_cutB[b];
    for (int i0 = 0; i0 < NPAD; i0 += 1024) {
        int i = i0 + tid;
        unsigned code = (i < N_ANCH) ? g_code[b*N_ANCH + i] : 0xFFFFFFFFu;
        bool pred = (i < N_ANCH) && ((int)(code >> 18) <= cutB);
        unsigned mm = __ballot_sync(FULL, pred);
        int pre = __popc(mm & ((1u << lane) - 1u));
        int wbase = 0;
        if (lane == 0 && mm) wbase = atomicAdd(&fCnt, __popc(mm));
        wbase = __shfl_sync(FULL, wbase, 0);
        if (pred) {
            int pos = wbase + pre;
            if (pos < FCAP)
                g_fkeys[b*FCAP + pos] = ((unsigned long long)code << 16) | (unsigned)i;
        }
    }
    __syncthreads();
    int total = fCnt;
    for (int j = tid; j < FCAP; j += 1024)
        if (j >= total) g_fkeys[b*FCAP + j] = ~0ull;
    __syncthreads();

    // bitonic sort of FCAP keys in gmem (single CTA; perf irrelevant)
    unsigned long long* Ak = &g_fkeys[b*FCAP];
    for (int k = 2; k <= FCAP; k <<= 1) {
        for (int j = k >> 1; j > 0; j >>= 1) {
            for (int i = tid; i < FCAP; i += 1024) {
                int ixj = i ^ j;
                if (ixj > i) {
                    bool up = ((i & k) == 0);
                    unsigned long long a = Ak[i], c = Ak[ixj];
                    if ((a > c) == up) { Ak[i] = c; Ak[ixj] = a; }
                }
            }
            __syncthreads();
        }
    }

    // greedy NMS over sorted top-PRE with exact IoU semantics
    __shared__ float4 kbox[POST];
    __shared__ float  karea[POST];
    __shared__ int kcnt, supp;
    if (tid == 0) kcnt = 0;
    __syncthreads();

    for (int r = 0; r < PRE; r++) {
        if (kcnt >= POST) break;
        unsigned long long key = Ak[r];
        unsigned code = (unsigned)((key >> 16) & 0x3FFFFFFFull);
        if (code == INV30) break;           // sorted: rest invalid/sentinel
        int idx = (int)(key & 0xFFFFull);
        float4 bx = g_boxes[b*N_ANCH + idx];
        float ar = (bx.z - bx.x + 1.0f) * (bx.w - bx.y + 1.0f);
        if (tid == 0) supp = 0;
        __syncthreads();
        int kc = kcnt;
        for (int t = tid; t < kc; t += 1024) {
            float4 bj = kbox[t];
            float xx1 = fmaxf(bx.x, bj.x);
            float yy1 = fmaxf(bx.y, bj.y);
            float xx2 = fminf(bx.z, bj.z);
            float yy2 = fminf(bx.w, bj.w);
            float iw = fmaxf(xx2 - xx1 + 1.0f, 0.0f);
            float ih = fmaxf(yy2 - yy1 + 1.0f, 0.0f);
            float inter = __fmul_rn(iw, ih);
            float sum   = __fadd_rn(ar, karea[t]);
            if (__fmul_rn(inter, 4.0f) >= sum) {
                float uni = __fsub_rn(sum, inter);
                float iou = __fdiv_rn(inter, uni);
                if (iou > NMS_THR) supp = 1;
            }
        }
        __syncthreads();
        if (!supp && tid == 0) { kbox[kcnt] = bx; karea[kcnt] = ar; kcnt = kcnt + 1; }
        __syncthreads();
    }

    int kc = kcnt;
    for (int r = tid; r < POST; r += 1024) {
        float* o = out + ((size_t)(b*POST + r))*5;
        if (r < kc) {
            float4 bx = kbox[r];
            o[0] = (float)b; o[1] = bx.x; o[2] = bx.y; o[3] = bx.z; o[4] = bx.w;
        } else {
            o[0] = (float)b; o[1] = 0.0f; o[2] = 0.0f; o[3] = 0.0f; o[4] = 0.0f;
        }
    }
}

// ---------------- launch: 6 kernels ----------------
extern "C" void kernel_launch(void* const* d_in, const int* in_sizes, int n_in,
                              void* d_out, int out_size)
{
    const float* scores  = (const float*)d_in[0];
    const float* deltas  = (const float*)d_in[1];
    const float* anchors = (const float*)d_in[2];
    const float* iminfo  = (const float*)d_in[3];
    float* out = (float*)d_out;

    const int total = B_ * N_ANCH;
    prep_kernel<<<(total + 255) / 256, 256>>>(scores, deltas, anchors, iminfo);
    cutoff_kernel<<<B_, 32>>>();
    compact_kernel<<<dim3(NBLK, B_), 256>>>();
    sort_kernel<<<B_, 1024>>>();

    dim3 m1grid(CH1, RT1, B_);
    mask1_kernel<<<m1grid, MROWS>>>();
    scan1_fb_kernel<<<B_, 1024>>>(out);
}

// round 13
// speedup vs baseline: 1.1070x; 1.0472x over previous
#include <cuda_runtime.h>
#include <cuda_bf16.h>
#include <cstdint>

// ---------------- problem constants ----------------
#define FH_   50
#define FW_   84
#define A_    12
#define B_    4
#define PIX   (FH_*FW_)        // 4200
#define N_ANCH (PIX*A_)        // 50400
#define PRE   6000
#define POST  300
#define NMS_THR 0.7f
#define NBUCK 4096
#define NBLK  197              // ceil(N_ANCH/256)
#define CAPA  4096             // fast-path compact capacity (top-2048 select)
#define FCAP  8192             // fallback compact capacity
#define INV30 0x3FFFFFFFu
// fast-path corner: top R1 rows x R1 cols
#define R1    2048
#define CH1   32               // R1/64 column words
#define RT1   8                // R1/256 row tiles
#define MROWS 256
#define NPAD  51200            // N_ANCH rounded up to 1024
// rank kernel shape
#define RK_CTAS 32             // CTAs per batch
#define RK_THR  128            // threads per CTA (RK_CTAS*RK_THR == CAPA)

static_assert(CH1*64 == R1 && RT1*MROWS == R1, "phase1 dims");
static_assert(NBLK*256 >= N_ANCH, "NBLK");
static_assert(N_ANCH < 65536, "index must fit in 16 bits");
static_assert(RK_CTAS*RK_THR == CAPA, "rank shape");

// Correctly-rounded float exp: short fp64 poly + Ziv check, rare libdevice
// fallback. Bit-identical to (float)exp((double)x) for every input.
__device__ __forceinline__ float exp_cr(float x) {
    double xd = (double)x;
    double t  = xd * 1.4426950408889634;
    int    k  = __double2int_rn(t);
    double kd = (double)k;
    double r  = __fma_rn(kd, -0.6931471805599453,    xd);
    r         = __fma_rn(kd, -2.3190468138462996e-17, r);
    double p = 2.505210838544172e-08;
    p = __fma_rn(p, r, 2.755731922398589e-07);
    p = __fma_rn(p, r, 2.7557319223985893e-06);
    p = __fma_rn(p, r, 2.48015873015873e-05);
    p = __fma_rn(p, r, 1.984126984126984e-04);
    p = __fma_rn(p, r, 1.3888888888888889e-03);
    p = __fma_rn(p, r, 8.333333333333333e-03);
    p = __fma_rn(p, r, 4.1666666666666664e-02);
    p = __fma_rn(p, r, 0.16666666666666666);
    p = __fma_rn(p, r, 0.5);
    p = __fma_rn(p, r, 1.0);
    p = __fma_rn(p, r, 1.0);
    double yd = p * __longlong_as_double((long long)(1023 + k) << 52);
    float flo = (float)(yd * (1.0 - 1.0e-12));
    float fhi = (float)(yd * (1.0 + 1.0e-12));
    if (flo == fhi) return flo;
    return (float)exp(xd);
}

// ---------------- static device scratch ----------------
__device__ float4             g_boxes[B_*N_ANCH];
__device__ unsigned int       g_code [B_*N_ANCH];
__device__ int                g_hist [B_*NBUCK];   // zero-init; re-zeroed by cutoff
__device__ int                g_cutA [B_];
__device__ int                g_cutB [B_];
__device__ int                g_cnt  [B_];         // compaction counter (zeroed by cutoff)
__device__ unsigned long long g_ckeys[B_*CAPA];    // sentinel-filled by prep
__device__ float4             g_sboxes[B_*R1];
__device__ float              g_sarea [B_*R1];
__device__ unsigned char      g_svalid[B_*R1];
// corner mask (zero-init; fully-lower words never written -> stay 0)
__device__ unsigned long long g_mask1[(size_t)B_*R1*CH1];
// fallback scratch (never touched on fast path)
__device__ unsigned long long g_fkeys[B_*FCAP];

// ---------------- kernel 1: softmax + decode + code + histogram + sentinel ----
__global__ void prep_kernel(const float* __restrict__ scores,
                            const float* __restrict__ deltas,
                            const float* __restrict__ anchors,
                            const float* __restrict__ iminfo)
{
    int idx = blockIdx.x * blockDim.x + threadIdx.x;
    if (idx >= B_*N_ANCH) return;

    // spare duty: sentinel-fill compact buffer for this replay
    if (idx < B_*CAPA) g_ckeys[idx] = ~0ull;

    int pix = idx % PIX;
    int ba  = idx / PIX;
    int b   = ba / A_;
    int a   = ba % A_;

    // softmax over (2a,2a+1): max-shift makes one exp exactly 1.0; single
    // E=exp(-|s1-s0|) reproduces the reference bitwise.
    const float* sp = scores + ((size_t)(b*2*A_ + 2*a))*PIX + pix;
    float s0 = sp[0];
    float s1 = sp[PIX];
    float dneg = (s1 >= s0) ? __fsub_rn(s0, s1) : __fsub_rn(s1, s0);
    float E     = exp_cr(dneg);
    float denom = __fadd_rn(E, 1.0f);
    float p = (s1 >= s0) ? __fdiv_rn(1.0f, denom) : __fdiv_rn(E, denom);

    const float* dp = deltas + ((size_t)(b*4*A_ + 4*a))*PIX + pix;
    float d0 = dp[0], d1 = dp[PIX], d2 = dp[2*PIX], d3 = dp[3*PIX];

    int i = pix*A_ + a;
    float4 an = reinterpret_cast<const float4*>(anchors)[i];

    float w  = an.z - an.x + 1.0f;
    float h  = an.w - an.y + 1.0f;
    float cx = __fadd_rn(an.x, __fmul_rn(0.5f, w));
    float cy = __fadd_rn(an.y, __fmul_rn(0.5f, h));
    float pcx = __fadd_rn(__fmul_rn(d0, w), cx);
    float pcy = __fadd_rn(__fmul_rn(d1, h), cy);
    float pw  = __fmul_rn(exp_cr(d2), w);
    float ph  = __fmul_rn(exp_cr(d3), h);
    float hx  = __fmul_rn(0.5f, pw);
    float hy  = __fmul_rn(0.5f, ph);
    float x1  = __fsub_rn(pcx, hx);
    float y1  = __fsub_rn(pcy, hy);
    float x2  = __fadd_rn(pcx, hx);
    float y2  = __fadd_rn(pcy, hy);

    float imh = iminfo[b*4+0], imw = iminfo[b*4+1];
    float sh  = iminfo[b*4+2], sw  = iminfo[b*4+3];
    float mw  = imw - 1.0f, mh = imh - 1.0f;
    x1 = fminf(fmaxf(x1, 0.0f), mw);
    y1 = fminf(fmaxf(y1, 0.0f), mh);
    x2 = fminf(fmaxf(x2, 0.0f), mw);
    y2 = fminf(fmaxf(y2, 0.0f), mh);

    float ws = x2 - x1 + 1.0f;
    float hs = y2 - y1 + 1.0f;
    bool valid = (ws >= __fmul_rn(16.0f, sw)) && (hs >= __fmul_rn(16.0f, sh));

    unsigned int code = valid ? (0x3F800000u - __float_as_uint(p)) : INV30;

    int gi = b*N_ANCH + i;
    g_code [gi] = code;
    g_boxes[gi] = make_float4(x1, y1, x2, y2);
    atomicAdd(&g_hist[b*NBUCK + (code >> 18)], 1);
}

// ---------------- kernel 2: cutoffs + hist re-zero + counter zero -------------
__global__ void cutoff_kernel()
{
    int b = blockIdx.x;
    int lane = threadIdx.x;                  // 32 threads
    const unsigned FULL = 0xFFFFFFFFu;
    int running = 0;
    int cutA = NBUCK - 1, cutB = NBUCK - 1;
    bool fA = false, fB = false;
    for (int it = 0; it < NBUCK/32; it++) {
        int v = g_hist[b*NBUCK + it*32 + lane];
        int s = v;
        #pragma unroll
        for (int d = 1; d < 32; d <<= 1) {
            int t = __shfl_up_sync(FULL, s, d);
            if (lane >= d) s += t;
        }
        int cum = running + s;
        if (!fA) {
            unsigned mm = __ballot_sync(FULL, cum >= R1);
            if (mm) { cutA = it*32 + __ffs(mm) - 1; fA = true; }
        }
        if (!fB) {
            unsigned mm = __ballot_sync(FULL, cum >= PRE);
            if (mm) { cutB = it*32 + __ffs(mm) - 1; fB = true; }
        }
        if (fA && fB) break;
        running += __shfl_sync(FULL, s, 31);
    }
    if (lane == 0) { g_cutA[b] = cutA; g_cutB[b] = cutB; g_cnt[b] = 0; }
    // re-zero the full histogram for the next graph replay (sole reader is us)
    for (int j = lane; j < NBUCK; j += 32) g_hist[b*NBUCK + j] = 0;
}

// ---------------- kernel 3: unordered warp-aggregated compaction --------------
// Order is irrelevant: key = (code<<16 | anchor_index) carries the exact
// (score, index) sort order, so any permutation ranks to the same sequence.
__global__ void compact_kernel()
{
    int blk = blockIdx.x, b = blockIdx.y;
    int tid = threadIdx.x;                  // 256 threads
    int lane = tid & 31;
    const unsigned FULL = 0xFFFFFFFFu;

    int i = blk*256 + tid;
    unsigned code = (i < N_ANCH) ? g_code[b*N_ANCH + i] : 0xFFFFFFFFu;
    int cutA = g_cutA[b];
    bool pred = (i < N_ANCH) && ((int)(code >> 18) <= cutA);
    unsigned mm = __ballot_sync(FULL, pred);
    int pre = __popc(mm & ((1u << lane) - 1u));
    int wbase = 0;
    if (lane == 0 && mm) wbase = atomicAdd(&g_cnt[b], __popc(mm));
    wbase = __shfl_sync(FULL, wbase, 0);
    if (pred) {
        int pos = wbase + pre;
        if (pos < CAPA)
            g_ckeys[b*CAPA + pos] = ((unsigned long long)code << 16) | (unsigned)i;
    }
}

// ---------------- kernel 4: whole-chip rank-count "sort" + fused gather -------
// rank(key) = #{ keys < key }. Keys unique -> ranks = exact stable-sort
// positions. cutA guarantees >= R1 selected keys, so ranks [0,R1) are each
// written exactly once.
__global__ void __launch_bounds__(RK_THR) rank_kernel()
{
    __shared__ unsigned long long sk[CAPA];   // 32 KB
    int cb = blockIdx.x;                      // item chunk, < RK_CTAS
    int b  = blockIdx.y;
    int tid = threadIdx.x;                    // RK_THR threads

    #pragma unroll
    for (int k = 0; k < CAPA/RK_THR; k++)
        sk[tid + k*RK_THR] = g_ckeys[b*CAPA + tid + k*RK_THR];
    __syncthreads();

    int item = cb*RK_THR + tid;               // < CAPA
    unsigned long long mykey = sk[item];
    if (mykey == ~0ull) return;               // sentinel slot

    int rank = 0;
    #pragma unroll 16
    for (int j = 0; j < CAPA; j++)
        rank += (sk[j] < mykey) ? 1 : 0;

    if (rank < R1) {
        unsigned code = (unsigned)((mykey >> 16) & 0x3FFFFFFFull);
        int idx = (int)(mykey & 0xFFFFull);
        float4 bx = g_boxes[b*N_ANCH + idx];
        float  ar = (bx.z - bx.x + 1.0f) * (bx.w - bx.y + 1.0f);
        g_sboxes[b*R1 + rank] = bx;
        g_sarea [b*R1 + rank] = ar;
        g_svalid[b*R1 + rank] = (code != INV30) ? 1 : 0;
    }
}

// ---------------- shared IoU bit computation ----------------
__device__ __forceinline__ unsigned long long iou_bits(
    float4 bi, float ai, const float4* cbox, const float* carea, int jmax)
{
    unsigned long long bits = 0ull;
    #pragma unroll 8
    for (int k = 0; k < jmax; k++) {
        float4 bj = cbox[k];
        float xx1 = fmaxf(bi.x, bj.x);
        float yy1 = fmaxf(bi.y, bj.y);
        float xx2 = fminf(bi.z, bj.z);
        float yy2 = fminf(bi.w, bj.w);
        float iw = fmaxf(xx2 - xx1 + 1.0f, 0.0f);
        float ih = fmaxf(yy2 - yy1 + 1.0f, 0.0f);
        float inter = __fmul_rn(iw, ih);
        float sum   = __fadd_rn(ai, carea[k]);
        // exact prefilter: iou>0.7 requires inter>0.41*sum; 4*inter>=sum is a
        // safe necessary condition -> kept-bit set is bit-identical
        if (__fmul_rn(inter, 4.0f) >= sum) {
            float uni = __fsub_rn(sum, inter);
            float iou = __fdiv_rn(inter, uni);
            if (iou > NMS_THR) bits |= (1ull << k);
        }
    }
    return bits;
}

// ---------------- kernel 5: corner mask (top R1 x R1) ----------------
__global__ void mask1_kernel()
{
    int cb = blockIdx.x;                    // column word, < CH1
    int rt = blockIdx.y;                    // row 256-tile, < RT1
    int b  = blockIdx.z;
    int j0 = cb * 64;
    if (j0 + 63 < rt * MROWS) return;       // fully-lower tile: words stay 0

    __shared__ float4 cbox[64];
    __shared__ float  carea[64];
    int t = threadIdx.x;
    if (t < 64) {
        cbox[t]  = g_sboxes[b*R1 + j0 + t];
        carea[t] = g_sarea [b*R1 + j0 + t];
    }
    __syncthreads();

    int i = rt * MROWS + t;                 // < R1
    int d = i - j0;
    size_t word = ((size_t)(b*R1 + i))*CH1 + cb;
    if (d >= 63) { g_mask1[word] = 0ull; return; }

    unsigned long long bits = iou_bits(g_sboxes[b*R1 + i], g_sarea[b*R1 + i],
                                       cbox, carea, 64);
    if (d >= 0) bits &= (~0ull) << (d + 1);
    g_mask1[word] = bits;
}

// ---------------- kernel 6: corner scan + inline exact fallback ----------------
__global__ void __launch_bounds__(1024) scan1_fb_kernel(float* __restrict__ out)
{
    int b    = blockIdx.x;
    int tid  = threadIdx.x;                 // 1024 threads
    int lane = tid & 31;
    int warp = tid >> 5;
    const unsigned FULL = 0xFFFFFFFFu;

    __shared__ unsigned long long removed[CH1];
    __shared__ int keptList[POST];
    __shared__ int sDone;

    // ---- warp 0: greedy scan over the corner mask ----
    if (warp == 0) {
        if (lane < CH1) removed[lane] = 0ull;
        __syncwarp();

        int kept = 0;
        for (int c = 0; c < CH1 && kept < POST; c++) {
            int r0 = c * 64;
            int ra = r0 + lane, rb2 = r0 + 32 + lane;

            unsigned lo = __ballot_sync(FULL, g_svalid[b*R1 + ra ] != 0);
            unsigned hi = __ballot_sync(FULL, g_svalid[b*R1 + rb2] != 0);
            unsigned long long validm = (unsigned long long)lo | ((unsigned long long)hi << 32);

            unsigned long long m0 = g_mask1[((size_t)(b*R1 + ra ))*CH1 + c];
            unsigned long long m1 = g_mask1[((size_t)(b*R1 + rb2))*CH1 + c];

            unsigned long long cand = validm & ~removed[c];
            unsigned long long keptbits = 0ull;
            while (cand && kept < POST) {
                int l = __ffsll((long long)cand) - 1;
                keptList[kept] = r0 + l;
                kept++;
                keptbits |= (1ull << l);
                unsigned long long intra = (l < 32) ? __shfl_sync(FULL, m0, l)
                                                    : __shfl_sync(FULL, m1, l - 32);
                cand &= ~intra;
                cand &= ~(1ull << l);
            }

            if (keptbits) {
                unsigned long long acc = 0ull;       // lane -> word (CH1==32)
                unsigned long long kb2 = keptbits;
                while (kb2) {
                    int l = __ffsll((long long)kb2) - 1;
                    kb2 &= kb2 - 1;
                    acc |= g_mask1[((size_t)(b*R1 + r0 + l))*CH1 + lane];
                }
                removed[lane] |= acc;
            }
            __syncwarp();
        }
        if (lane == 0)
            sDone = (kept >= POST && g_cnt[b] <= CAPA) ? 1 : 0;
    }
    __syncthreads();

    if (sDone) {
        for (int r = tid; r < POST; r += 1024) {
            float* o = out + ((size_t)(b*POST + r))*5;
            float4 bx = g_sboxes[b*R1 + keptList[r]];
            o[0] = (float)b; o[1] = bx.x; o[2] = bx.y; o[3] = bx.z; o[4] = bx.w;
        }
        return;
    }

    // ================= exact fallback (not expected on real data) ============
    __shared__ int fCnt;
    if (tid == 0) fCnt = 0;
    __syncthreads();

    int cutB = g_cutB[b];
    for (int i0 = 0; i0 < NPAD; i0 += 1024) {
        int i = i0 + tid;
        unsigned code = (i < N_ANCH) ? g_code[b*N_ANCH + i] : 0xFFFFFFFFu;
        bool pred = (i < N_ANCH) && ((int)(code >> 18) <= cutB);
        unsigned mm = __ballot_sync(FULL, pred);
        int pre = __popc(mm & ((1u << lane) - 1u));
        int wbase = 0;
        if (lane == 0 && mm) wbase = atomicAdd(&fCnt, __popc(mm));
        wbase = __shfl_sync(FULL, wbase, 0);
        if (pred) {
            int pos = wbase + pre;
            if (pos < FCAP)
                g_fkeys[b*FCAP + pos] = ((unsigned long long)code << 16) | (unsigned)i;
        }
    }
    __syncthreads();
    int total = fCnt;
    for (int j = tid; j < FCAP; j += 1024)
        if (j >= total) g_fkeys[b*FCAP + j] = ~0ull;
    __syncthreads();

    // bitonic sort of FCAP keys in gmem (single CTA; perf irrelevant)
    unsigned long long* Ak = &g_fkeys[b*FCAP];
    for (int k = 2; k <= FCAP; k <<= 1) {
        for (int j = k >> 1; j > 0; j >>= 1) {
            for (int i = tid; i < FCAP; i += 1024) {
                int ixj = i ^ j;
                if (ixj > i) {
                    bool up = ((i & k) == 0);
                    unsigned long long a = Ak[i], c = Ak[ixj];
                    if ((a > c) == up) { Ak[i] = c; Ak[ixj] = a; }
                }
            }
            __syncthreads();
        }
    }

    // greedy NMS over sorted top-PRE with exact IoU semantics
    __shared__ float4 kbox[POST];
    __shared__ float  karea[POST];
    __shared__ int kcnt, supp;
    if (tid == 0) kcnt = 0;
    __syncthreads();

    for (int r = 0; r < PRE; r++) {
        if (kcnt >= POST) break;
        unsigned long long key = Ak[r];
        unsigned code = (unsigned)((key >> 16) & 0x3FFFFFFFull);
        if (code == INV30) break;           // sorted: rest invalid/sentinel
        int idx = (int)(key & 0xFFFFull);
        float4 bx = g_boxes[b*N_ANCH + idx];
        float ar = (bx.z - bx.x + 1.0f) * (bx.w - bx.y + 1.0f);
        if (tid == 0) supp = 0;
        __syncthreads();
        int kc = kcnt;
        for (int t = tid; t < kc; t += 1024) {
            float4 bj = kbox[t];
            float xx1 = fmaxf(bx.x, bj.x);
            float yy1 = fmaxf(bx.y, bj.y);
            float xx2 = fminf(bx.z, bj.z);
            float yy2 = fminf(bx.w, bj.w);
            float iw = fmaxf(xx2 - xx1 + 1.0f, 0.0f);
            float ih = fmaxf(yy2 - yy1 + 1.0f, 0.0f);
            float inter = __fmul_rn(iw, ih);
            float sum   = __fadd_rn(ar, karea[t]);
            if (__fmul_rn(inter, 4.0f) >= sum) {
                float uni = __fsub_rn(sum, inter);
                float iou = __fdiv_rn(inter, uni);
                if (iou > NMS_THR) supp = 1;
            }
        }
        __syncthreads();
        if (!supp && tid == 0) { kbox[kcnt] = bx; karea[kcnt] = ar; kcnt = kcnt + 1; }
        __syncthreads();
    }

    int kc = kcnt;
    for (int r = tid; r < POST; r += 1024) {
        float* o = out + ((size_t)(b*POST + r))*5;
        if (r < kc) {
            float4 bx = kbox[r];
            o[0] = (float)b; o[1] = bx.x; o[2] = bx.y; o[3] = bx.z; o[4] = bx.w;
        } else {
            o[0] = (float)b; o[1] = 0.0f; o[2] = 0.0f; o[3] = 0.0f; o[4] = 0.0f;
        }
    }
}

// ---------------- launch: 6 kernels ----------------
extern "C" void kernel_launch(void* const* d_in, const int* in_sizes, int n_in,
                              void* d_out, int out_size)
{
    const float* scores  = (const float*)d_in[0];
    const float* deltas  = (const float*)d_in[1];
    const float* anchors = (const float*)d_in[2];
    const float* iminfo  = (const float*)d_in[3];
    float* out = (float*)d_out;

    const int total = B_ * N_ANCH;
    prep_kernel<<<(total + 255) / 256, 256>>>(scores, deltas, anchors, iminfo);
    cutoff_kernel<<<B_, 32>>>();
    compact_kernel<<<dim3(NBLK, B_), 256>>>();
    rank_kernel<<<dim3(RK_CTAS, B_), RK_THR>>>();

    dim3 m1grid(CH1, RT1, B_);
    mask1_kernel<<<m1grid, MROWS>>>();
    scan1_fb_kernel<<<B_, 1024>>>(out);
}

// round 14
// speedup vs baseline: 1.1444x; 1.0338x over previous
#include <cuda_runtime.h>
#include <cuda_bf16.h>
#include <cstdint>

// ---------------- problem constants ----------------
#define FH_   50
#define FW_   84
#define A_    12
#define B_    4
#define PIX   (FH_*FW_)        // 4200
#define N_ANCH (PIX*A_)        // 50400
#define PRE   6000
#define POST  300
#define NMS_THR 0.7f
#define NBUCK 4096
#define NBLK  197              // ceil(N_ANCH/256)
#define CAPA  4096             // fast-path compact capacity (top-2048 select)
#define FCAP  8192             // fallback compact capacity
#define INV30 0x3FFFFFFFu
// fast-path corner: top R1 rows x R1 cols
#define R1    2048
#define CH1   32               // R1/64 column words
#define RT1   8                // R1/256 row tiles
#define MROWS 256
#define NPAD  51200            // N_ANCH rounded up to 1024
// rank kernel shape
#define RK_CTAS 32             // CTAs per batch
#define RK_THR  128            // threads per CTA (RK_CTAS*RK_THR == CAPA)

static_assert(CH1*64 == R1 && RT1*MROWS == R1, "phase1 dims");
static_assert(NBLK*256 >= N_ANCH, "NBLK");
static_assert(N_ANCH < 65536, "index must fit in 16 bits");
static_assert(RK_CTAS*RK_THR == CAPA, "rank shape");

// Correctly-rounded float exp: short fp64 poly + Ziv check, rare libdevice
// fallback. Bit-identical to (float)exp((double)x) for every input.
__device__ __forceinline__ float exp_cr(float x) {
    double xd = (double)x;
    double t  = xd * 1.4426950408889634;
    int    k  = __double2int_rn(t);
    double kd = (double)k;
    double r  = __fma_rn(kd, -0.6931471805599453,    xd);
    r         = __fma_rn(kd, -2.3190468138462996e-17, r);
    double p = 2.505210838544172e-08;
    p = __fma_rn(p, r, 2.755731922398589e-07);
    p = __fma_rn(p, r, 2.7557319223985893e-06);
    p = __fma_rn(p, r, 2.48015873015873e-05);
    p = __fma_rn(p, r, 1.984126984126984e-04);
    p = __fma_rn(p, r, 1.3888888888888889e-03);
    p = __fma_rn(p, r, 8.333333333333333e-03);
    p = __fma_rn(p, r, 4.1666666666666664e-02);
    p = __fma_rn(p, r, 0.16666666666666666);
    p = __fma_rn(p, r, 0.5);
    p = __fma_rn(p, r, 1.0);
    p = __fma_rn(p, r, 1.0);
    double yd = p * __longlong_as_double((long long)(1023 + k) << 52);
    float flo = (float)(yd * (1.0 - 1.0e-12));
    float fhi = (float)(yd * (1.0 + 1.0e-12));
    if (flo == fhi) return flo;
    return (float)exp(xd);
}

// ---------------- static device scratch ----------------
__device__ float4             g_boxes[B_*N_ANCH];
__device__ unsigned int       g_code [B_*N_ANCH];
__device__ int                g_hist [B_*NBUCK];   // zero-init; re-zeroed by cutoff
__device__ int                g_cutA [B_];
__device__ int                g_cutB [B_];
__device__ int                g_cnt  [B_];         // compaction counter (zeroed by cutoff)
__device__ unsigned long long g_ckeys[B_*CAPA];    // sentinel-filled by prep
__device__ float4             g_sboxes[B_*R1];
__device__ float              g_sarea [B_*R1];
__device__ unsigned char      g_svalid[B_*R1];
// corner mask (zero-init; fully-lower words never written -> stay 0)
__device__ unsigned long long g_mask1[(size_t)B_*R1*CH1];
// fallback scratch (never touched on fast path)
__device__ unsigned long long g_fkeys[B_*FCAP];

// ---------------- kernel 1: softmax + decode + code + histogram + sentinel ----
__global__ void prep_kernel(const float* __restrict__ scores,
                            const float* __restrict__ deltas,
                            const float* __restrict__ anchors,
                            const float* __restrict__ iminfo)
{
    int idx = blockIdx.x * blockDim.x + threadIdx.x;
    if (idx >= B_*N_ANCH) return;

    // spare duty: sentinel-fill compact buffer for this replay
    if (idx < B_*CAPA) g_ckeys[idx] = ~0ull;

    int pix = idx % PIX;
    int ba  = idx / PIX;
    int b   = ba / A_;
    int a   = ba % A_;

    // softmax over (2a,2a+1): max-shift makes one exp exactly 1.0; single
    // E=exp(-|s1-s0|) reproduces the reference bitwise.
    const float* sp = scores + ((size_t)(b*2*A_ + 2*a))*PIX + pix;
    float s0 = sp[0];
    float s1 = sp[PIX];
    float dneg = (s1 >= s0) ? __fsub_rn(s0, s1) : __fsub_rn(s1, s0);
    float E     = exp_cr(dneg);
    float denom = __fadd_rn(E, 1.0f);
    float p = (s1 >= s0) ? __fdiv_rn(1.0f, denom) : __fdiv_rn(E, denom);

    const float* dp = deltas + ((size_t)(b*4*A_ + 4*a))*PIX + pix;
    float d0 = dp[0], d1 = dp[PIX], d2 = dp[2*PIX], d3 = dp[3*PIX];

    int i = pix*A_ + a;
    float4 an = reinterpret_cast<const float4*>(anchors)[i];

    float w  = an.z - an.x + 1.0f;
    float h  = an.w - an.y + 1.0f;
    float cx = __fadd_rn(an.x, __fmul_rn(0.5f, w));
    float cy = __fadd_rn(an.y, __fmul_rn(0.5f, h));
    float pcx = __fadd_rn(__fmul_rn(d0, w), cx);
    float pcy = __fadd_rn(__fmul_rn(d1, h), cy);
    float pw  = __fmul_rn(exp_cr(d2), w);
    float ph  = __fmul_rn(exp_cr(d3), h);
    float hx  = __fmul_rn(0.5f, pw);
    float hy  = __fmul_rn(0.5f, ph);
    float x1  = __fsub_rn(pcx, hx);
    float y1  = __fsub_rn(pcy, hy);
    float x2  = __fadd_rn(pcx, hx);
    float y2  = __fadd_rn(pcy, hy);

    float imh = iminfo[b*4+0], imw = iminfo[b*4+1];
    float sh  = iminfo[b*4+2], sw  = iminfo[b*4+3];
    float mw  = imw - 1.0f, mh = imh - 1.0f;
    x1 = fminf(fmaxf(x1, 0.0f), mw);
    y1 = fminf(fmaxf(y1, 0.0f), mh);
    x2 = fminf(fmaxf(x2, 0.0f), mw);
    y2 = fminf(fmaxf(y2, 0.0f), mh);

    float ws = x2 - x1 + 1.0f;
    float hs = y2 - y1 + 1.0f;
    bool valid = (ws >= __fmul_rn(16.0f, sw)) && (hs >= __fmul_rn(16.0f, sh));

    unsigned int code = valid ? (0x3F800000u - __float_as_uint(p)) : INV30;

    int gi = b*N_ANCH + i;
    g_code [gi] = code;
    g_boxes[gi] = make_float4(x1, y1, x2, y2);
    atomicAdd(&g_hist[b*NBUCK + (code >> 18)], 1);
}

// ---------------- kernel 2: cutoffs + hist re-zero + counter zero -------------
__global__ void cutoff_kernel()
{
    int b = blockIdx.x;
    int lane = threadIdx.x;                  // 32 threads
    const unsigned FULL = 0xFFFFFFFFu;
    int running = 0;
    int cutA = NBUCK - 1, cutB = NBUCK - 1;
    bool fA = false, fB = false;
    for (int it = 0; it < NBUCK/32; it++) {
        int v = g_hist[b*NBUCK + it*32 + lane];
        int s = v;
        #pragma unroll
        for (int d = 1; d < 32; d <<= 1) {
            int t = __shfl_up_sync(FULL, s, d);
            if (lane >= d) s += t;
        }
        int cum = running + s;
        if (!fA) {
            unsigned mm = __ballot_sync(FULL, cum >= R1);
            if (mm) { cutA = it*32 + __ffs(mm) - 1; fA = true; }
        }
        if (!fB) {
            unsigned mm = __ballot_sync(FULL, cum >= PRE);
            if (mm) { cutB = it*32 + __ffs(mm) - 1; fB = true; }
        }
        if (fA && fB) break;
        running += __shfl_sync(FULL, s, 31);
    }
    if (lane == 0) { g_cutA[b] = cutA; g_cutB[b] = cutB; g_cnt[b] = 0; }
    // re-zero the full histogram for the next graph replay (sole reader is us)
    for (int j = lane; j < NBUCK; j += 32) g_hist[b*NBUCK + j] = 0;
}

// ---------------- kernel 3: unordered warp-aggregated compaction --------------
// Order is irrelevant: key = (code<<16 | anchor_index) carries the exact
// (score, index) sort order, so any permutation ranks to the same sequence.
__global__ void compact_kernel()
{
    int blk = blockIdx.x, b = blockIdx.y;
    int tid = threadIdx.x;                  // 256 threads
    int lane = tid & 31;
    const unsigned FULL = 0xFFFFFFFFu;

    int i = blk*256 + tid;
    unsigned code = (i < N_ANCH) ? g_code[b*N_ANCH + i] : 0xFFFFFFFFu;
    int cutA = g_cutA[b];
    bool pred = (i < N_ANCH) && ((int)(code >> 18) <= cutA);
    unsigned mm = __ballot_sync(FULL, pred);
    int pre = __popc(mm & ((1u << lane) - 1u));
    int wbase = 0;
    if (lane == 0 && mm) wbase = atomicAdd(&g_cnt[b], __popc(mm));
    wbase = __shfl_sync(FULL, wbase, 0);
    if (pred) {
        int pos = wbase + pre;
        if (pos < CAPA)
            g_ckeys[b*CAPA + pos] = ((unsigned long long)code << 16) | (unsigned)i;
    }
}

// ---------------- kernel 4: whole-chip rank-count "sort" + fused gather -------
// rank(key) = #{ keys < key }. Keys unique -> ranks = exact stable-sort
// positions. Sentinels (~0ull) never compare below a real key, so restricting
// the compare loop to the live prefix [0, cnt) yields identical ranks.
__global__ void __launch_bounds__(RK_THR) rank_kernel()
{
    __shared__ __align__(16) unsigned long long sk[CAPA];   // 32 KB
    int cb = blockIdx.x;                      // item chunk, < RK_CTAS
    int b  = blockIdx.y;
    int tid = threadIdx.x;                    // RK_THR threads

    int cnt = min(g_cnt[b], CAPA);
    if (cb * RK_THR >= cnt) return;           // whole chunk past live prefix

    // stage live keys (+1 sentinel pad for the even bound)
    int n2 = (cnt + 1) & ~1;                  // even upper bound <= CAPA
    for (int k2 = tid; k2 < n2; k2 += RK_THR)
        sk[k2] = g_ckeys[b*CAPA + k2];
    __syncthreads();

    int item = cb*RK_THR + tid;
    if (item >= cnt) return;
    unsigned long long mykey = sk[item];

    int r0 = 0, r1 = 0;
    const ulonglong2* skv = reinterpret_cast<const ulonglong2*>(sk);
    #pragma unroll 8
    for (int j = 0; j < n2/2; j++) {
        ulonglong2 v = skv[j];
        r0 += (v.x < mykey) ? 1 : 0;
        r1 += (v.y < mykey) ? 1 : 0;
    }
    int rank = r0 + r1;

    if (rank < R1) {
        unsigned code = (unsigned)((mykey >> 16) & 0x3FFFFFFFull);
        int idx = (int)(mykey & 0xFFFFull);
        float4 bx = g_boxes[b*N_ANCH + idx];
        float  ar = (bx.z - bx.x + 1.0f) * (bx.w - bx.y + 1.0f);
        g_sboxes[b*R1 + rank] = bx;
        g_sarea [b*R1 + rank] = ar;
        g_svalid[b*R1 + rank] = (code != INV30) ? 1 : 0;
    }
}

// ---------------- shared IoU bit computation ----------------
__device__ __forceinline__ unsigned long long iou_bits(
    float4 bi, float ai, const float4* cbox, const float* carea, int jmax)
{
    unsigned long long bits = 0ull;
    #pragma unroll 8
    for (int k = 0; k < jmax; k++) {
        float4 bj = cbox[k];
        float xx1 = fmaxf(bi.x, bj.x);
        float yy1 = fmaxf(bi.y, bj.y);
        float xx2 = fminf(bi.z, bj.z);
        float yy2 = fminf(bi.w, bj.w);
        float iw = fmaxf(xx2 - xx1 + 1.0f, 0.0f);
        float ih = fmaxf(yy2 - yy1 + 1.0f, 0.0f);
        float inter = __fmul_rn(iw, ih);
        float sum   = __fadd_rn(ai, carea[k]);
        // exact prefilter: iou>0.7 requires inter>0.41*sum; 4*inter>=sum is a
        // safe necessary condition -> kept-bit set is bit-identical
        if (__fmul_rn(inter, 4.0f) >= sum) {
            float uni = __fsub_rn(sum, inter);
            float iou = __fdiv_rn(inter, uni);
            if (iou > NMS_THR) bits |= (1ull << k);
        }
    }
    return bits;
}

// ---------------- kernel 5: corner mask (top R1 x R1) ----------------
__global__ void mask1_kernel()
{
    int cb = blockIdx.x;                    // column word, < CH1
    int rt = blockIdx.y;                    // row 256-tile, < RT1
    int b  = blockIdx.z;
    int j0 = cb * 64;
    if (j0 + 63 < rt * MROWS) return;       // fully-lower tile: words stay 0

    __shared__ float4 cbox[64];
    __shared__ float  carea[64];
    int t = threadIdx.x;
    if (t < 64) {
        cbox[t]  = g_sboxes[b*R1 + j0 + t];
        carea[t] = g_sarea [b*R1 + j0 + t];
    }
    __syncthreads();

    int i = rt * MROWS + t;                 // < R1
    int d = i - j0;
    size_t word = ((size_t)(b*R1 + i))*CH1 + cb;
    if (d >= 63) { g_mask1[word] = 0ull; return; }

    unsigned long long bits = iou_bits(g_sboxes[b*R1 + i], g_sarea[b*R1 + i],
                                       cbox, carea, 64);
    if (d >= 0) bits &= (~0ull) << (d + 1);
    g_mask1[word] = bits;
}

// ---------------- kernel 6: corner scan + inline exact fallback ----------------
__global__ void __launch_bounds__(1024) scan1_fb_kernel(float* __restrict__ out)
{
    int b    = blockIdx.x;
    int tid  = threadIdx.x;                 // 1024 threads
    int lane = tid & 31;
    int warp = tid >> 5;
    const unsigned FULL = 0xFFFFFFFFu;

    __shared__ unsigned long long removed[CH1];
    __shared__ int keptList[POST];
    __shared__ int sDone;

    // ---- warp 0: greedy scan over the corner mask ----
    if (warp == 0) {
        if (lane < CH1) removed[lane] = 0ull;
        __syncwarp();

        int kept = 0;
        for (int c = 0; c < CH1 && kept < POST; c++) {
            int r0 = c * 64;
            int ra = r0 + lane, rb2 = r0 + 32 + lane;

            unsigned lo = __ballot_sync(FULL, g_svalid[b*R1 + ra ] != 0);
            unsigned hi = __ballot_sync(FULL, g_svalid[b*R1 + rb2] != 0);
            unsigned long long validm = (unsigned long long)lo | ((unsigned long long)hi << 32);

            unsigned long long m0 = g_mask1[((size_t)(b*R1 + ra ))*CH1 + c];
            unsigned long long m1 = g_mask1[((size_t)(b*R1 + rb2))*CH1 + c];

            unsigned long long cand = validm & ~removed[c];
            unsigned long long keptbits = 0ull;
            while (cand && kept < POST) {
                int l = __ffsll((long long)cand) - 1;
                keptList[kept] = r0 + l;
                kept++;
                keptbits |= (1ull << l);
                unsigned long long intra = (l < 32) ? __shfl_sync(FULL, m0, l)
                                                    : __shfl_sync(FULL, m1, l - 32);
                cand &= ~intra;
                cand &= ~(1ull << l);
            }

            if (keptbits) {
                unsigned long long acc = 0ull;       // lane -> word (CH1==32)
                unsigned long long kb2 = keptbits;
                while (kb2) {
                    int l = __ffsll((long long)kb2) - 1;
                    kb2 &= kb2 - 1;
                    acc |= g_mask1[((size_t)(b*R1 + r0 + l))*CH1 + lane];
                }
                removed[lane] |= acc;
            }
            __syncwarp();
        }
        if (lane == 0)
            sDone = (kept >= POST && g_cnt[b] <= CAPA) ? 1 : 0;
    }
    __syncthreads();

    if (sDone) {
        for (int r = tid; r < POST; r += 1024) {
            float* o = out + ((size_t)(b*POST + r))*5;
            float4 bx = g_sboxes[b*R1 + keptList[r]];
            o[0] = (float)b; o[1] = bx.x; o[2] = bx.y; o[3] = bx.z; o[4] = bx.w;
        }
        return;
    }

    // ================= exact fallback (not expected on real data) ============
    __shared__ int fCnt;
    if (tid == 0) fCnt = 0;
    __syncthreads();

    int cutB = g_cutB[b];
    for (int i0 = 0; i0 < NPAD; i0 += 1024) {
        int i = i0 + tid;
        unsigned code = (i < N_ANCH) ? g_code[b*N_ANCH + i] : 0xFFFFFFFFu;
        bool pred = (i < N_ANCH) && ((int)(code >> 18) <= cutB);
        unsigned mm = __ballot_sync(FULL, pred);
        int pre = __popc(mm & ((1u << lane) - 1u));
        int wbase = 0;
        if (lane == 0 && mm) wbase = atomicAdd(&fCnt, __popc(mm));
        wbase = __shfl_sync(FULL, wbase, 0);
        if (pred) {
            int pos = wbase + pre;
            if (pos < FCAP)
                g_fkeys[b*FCAP + pos] = ((unsigned long long)code << 16) | (unsigned)i;
        }
    }
    __syncthreads();
    int total = fCnt;
    for (int j = tid; j < FCAP; j += 1024)
        if (j >= total) g_fkeys[b*FCAP + j] = ~0ull;
    __syncthreads();

    // bitonic sort of FCAP keys in gmem (single CTA; perf irrelevant)
    unsigned long long* Ak = &g_fkeys[b*FCAP];
    for (int k = 2; k <= FCAP; k <<= 1) {
        for (int j = k >> 1; j > 0; j >>= 1) {
            for (int i = tid; i < FCAP; i += 1024) {
                int ixj = i ^ j;
                if (ixj > i) {
                    bool up = ((i & k) == 0);
                    unsigned long long a = Ak[i], c = Ak[ixj];
                    if ((a > c) == up) { Ak[i] = c; Ak[ixj] = a; }
                }
            }
            __syncthreads();
        }
    }

    // greedy NMS over sorted top-PRE with exact IoU semantics
    __shared__ float4 kbox[POST];
    __shared__ float  karea[POST];
    __shared__ int kcnt, supp;
    if (tid == 0) kcnt = 0;
    __syncthreads();

    for (int r = 0; r < PRE; r++) {
        if (kcnt >= POST) break;
        unsigned long long key = Ak[r];
        unsigned code = (unsigned)((key >> 16) & 0x3FFFFFFFull);
        if (code == INV30) break;           // sorted: rest invalid/sentinel
        int idx = (int)(key & 0xFFFFull);
        float4 bx = g_boxes[b*N_ANCH + idx];
        float ar = (bx.z - bx.x + 1.0f) * (bx.w - bx.y + 1.0f);
        if (tid == 0) supp = 0;
        __syncthreads();
        int kc = kcnt;
        for (int t = tid; t < kc; t += 1024) {
            float4 bj = kbox[t];
            float xx1 = fmaxf(bx.x, bj.x);
            float yy1 = fmaxf(bx.y, bj.y);
            float xx2 = fminf(bx.z, bj.z);
            float yy2 = fminf(bx.w, bj.w);
            float iw = fmaxf(xx2 - xx1 + 1.0f, 0.0f);
            float ih = fmaxf(yy2 - yy1 + 1.0f, 0.0f);
            float inter = __fmul_rn(iw, ih);
            float sum   = __fadd_rn(ar, karea[t]);
            if (__fmul_rn(inter, 4.0f) >= sum) {
                float uni = __fsub_rn(sum, inter);
                float iou = __fdiv_rn(inter, uni);
                if (iou > NMS_THR) supp = 1;
            }
        }
        __syncthreads();
        if (!supp && tid == 0) { kbox[kcnt] = bx; karea[kcnt] = ar; kcnt = kcnt + 1; }
        __syncthreads();
    }

    int kc = kcnt;
    for (int r = tid; r < POST; r += 1024) {
        float* o = out + ((size_t)(b*POST + r))*5;
        if (r < kc) {
            float4 bx = kbox[r];
            o[0] = (float)b; o[1] = bx.x; o[2] = bx.y; o[3] = bx.z; o[4] = bx.w;
        } else {
            o[0] = (float)b; o[1] = 0.0f; o[2] = 0.0f; o[3] = 0.0f; o[4] = 0.0f;
        }
    }
}

// ---------------- launch: 6 kernels ----------------
extern "C" void kernel_launch(void* const* d_in, const int* in_sizes, int n_in,
                              void* d_out, int out_size)
{
    const float* scores  = (const float*)d_in[0];
    const float* deltas  = (const float*)d_in[1];
    const float* anchors = (const float*)d_in[2];
    const float* iminfo  = (const float*)d_in[3];
    float* out = (float*)d_out;

    const int total = B_ * N_ANCH;
    prep_kernel<<<(total + 255) / 256, 256>>>(scores, deltas, anchors, iminfo);
    cutoff_kernel<<<B_, 32>>>();
    compact_kernel<<<dim3(NBLK, B_), 256>>>();
    rank_kernel<<<dim3(RK_CTAS, B_), RK_THR>>>();

    dim3 m1grid(CH1, RT1, B_);
    mask1_kernel<<<m1grid, MROWS>>>();
    scan1_fb_kernel<<<B_, 1024>>>(out);
}

// round 15
// speedup vs baseline: 1.1704x; 1.0227x over previous
#include <cuda_runtime.h>
#include <cuda_bf16.h>
#include <cstdint>

// ---------------- problem constants ----------------
#define FH_   50
#define FW_   84
#define A_    12
#define B_    4
#define PIX   (FH_*FW_)        // 4200
#define N_ANCH (PIX*A_)        // 50400
#define PRE   6000
#define POST  300
#define NMS_THR 0.7f
#define NBUCK 4096
#define NBLK  197              // ceil(N_ANCH/256)
#define CAPA  4096             // fast-path compact capacity (top-2048 select)
#define FCAP  8192             // fallback compact capacity
#define INV30 0x3FFFFFFFu
// fast-path corner: top R1 rows x R1 cols
#define R1    2048
#define CH1   32               // R1/64 column words
#define RT1   8                // R1/256 row tiles
#define MROWS 256
#define NPAD  51200            // N_ANCH rounded up to 1024
// rank kernel shape: 128 items per CTA, 4 threads per item
#define RK_CTAS 32             // CTAs per batch
#define RK_THR  512            // threads per CTA

static_assert(CH1*64 == R1 && RT1*MROWS == R1, "phase1 dims");
static_assert(NBLK*256 >= N_ANCH, "NBLK");
static_assert(N_ANCH < 65536, "index must fit in 16 bits");
static_assert(RK_CTAS*(RK_THR/4) == CAPA, "rank shape");

// Correctly-rounded float exp: short fp64 poly + Ziv check, rare libdevice
// fallback. Bit-identical to (float)exp((double)x) for every input.
__device__ __forceinline__ float exp_cr(float x) {
    double xd = (double)x;
    double t  = xd * 1.4426950408889634;
    int    k  = __double2int_rn(t);
    double kd = (double)k;
    double r  = __fma_rn(kd, -0.6931471805599453,    xd);
    r         = __fma_rn(kd, -2.3190468138462996e-17, r);
    double p = 2.505210838544172e-08;
    p = __fma_rn(p, r, 2.755731922398589e-07);
    p = __fma_rn(p, r, 2.7557319223985893e-06);
    p = __fma_rn(p, r, 2.48015873015873e-05);
    p = __fma_rn(p, r, 1.984126984126984e-04);
    p = __fma_rn(p, r, 1.3888888888888889e-03);
    p = __fma_rn(p, r, 8.333333333333333e-03);
    p = __fma_rn(p, r, 4.1666666666666664e-02);
    p = __fma_rn(p, r, 0.16666666666666666);
    p = __fma_rn(p, r, 0.5);
    p = __fma_rn(p, r, 1.0);
    p = __fma_rn(p, r, 1.0);
    double yd = p * __longlong_as_double((long long)(1023 + k) << 52);
    float flo = (float)(yd * (1.0 - 1.0e-12));
    float fhi = (float)(yd * (1.0 + 1.0e-12));
    if (flo == fhi) return flo;
    return (float)exp(xd);
}

// ---------------- static device scratch ----------------
__device__ float4             g_boxes[B_*N_ANCH];
__device__ unsigned int       g_code [B_*N_ANCH];
__device__ int                g_hist [B_*NBUCK];   // zero-init; re-zeroed by cutoff
__device__ int                g_cutA [B_];
__device__ int                g_cutB [B_];
__device__ int                g_cnt  [B_];         // compaction counter (zeroed by cutoff)
__device__ unsigned long long g_ckeys[B_*CAPA];    // sentinel-filled by prep
__device__ float4             g_sboxes[B_*R1];
__device__ float              g_sarea [B_*R1];
__device__ unsigned char      g_svalid[B_*R1];
// corner mask (zero-init; fully-lower words never written -> stay 0)
__device__ unsigned long long g_mask1[(size_t)B_*R1*CH1];
// fallback scratch (never touched on fast path)
__device__ unsigned long long g_fkeys[B_*FCAP];

// ---------------- kernel 1: softmax + decode + code + histogram + sentinel ----
__global__ void prep_kernel(const float* __restrict__ scores,
                            const float* __restrict__ deltas,
                            const float* __restrict__ anchors,
                            const float* __restrict__ iminfo)
{
    int idx = blockIdx.x * blockDim.x + threadIdx.x;
    if (idx >= B_*N_ANCH) return;

    // spare duty: sentinel-fill compact buffer for this replay
    if (idx < B_*CAPA) g_ckeys[idx] = ~0ull;

    int pix = idx % PIX;
    int ba  = idx / PIX;
    int b   = ba / A_;
    int a   = ba % A_;

    // softmax over (2a,2a+1): max-shift makes one exp exactly 1.0; single
    // E=exp(-|s1-s0|) reproduces the reference bitwise.
    const float* sp = scores + ((size_t)(b*2*A_ + 2*a))*PIX + pix;
    float s0 = sp[0];
    float s1 = sp[PIX];
    float dneg = (s1 >= s0) ? __fsub_rn(s0, s1) : __fsub_rn(s1, s0);
    float E     = exp_cr(dneg);
    float denom = __fadd_rn(E, 1.0f);
    float p = (s1 >= s0) ? __fdiv_rn(1.0f, denom) : __fdiv_rn(E, denom);

    const float* dp = deltas + ((size_t)(b*4*A_ + 4*a))*PIX + pix;
    float d0 = dp[0], d1 = dp[PIX], d2 = dp[2*PIX], d3 = dp[3*PIX];

    int i = pix*A_ + a;
    float4 an = reinterpret_cast<const float4*>(anchors)[i];

    float w  = an.z - an.x + 1.0f;
    float h  = an.w - an.y + 1.0f;
    float cx = __fadd_rn(an.x, __fmul_rn(0.5f, w));
    float cy = __fadd_rn(an.y, __fmul_rn(0.5f, h));
    float pcx = __fadd_rn(__fmul_rn(d0, w), cx);
    float pcy = __fadd_rn(__fmul_rn(d1, h), cy);
    float pw  = __fmul_rn(exp_cr(d2), w);
    float ph  = __fmul_rn(exp_cr(d3), h);
    float hx  = __fmul_rn(0.5f, pw);
    float hy  = __fmul_rn(0.5f, ph);
    float x1  = __fsub_rn(pcx, hx);
    float y1  = __fsub_rn(pcy, hy);
    float x2  = __fadd_rn(pcx, hx);
    float y2  = __fadd_rn(pcy, hy);

    float imh = iminfo[b*4+0], imw = iminfo[b*4+1];
    float sh  = iminfo[b*4+2], sw  = iminfo[b*4+3];
    float mw  = imw - 1.0f, mh = imh - 1.0f;
    x1 = fminf(fmaxf(x1, 0.0f), mw);
    y1 = fminf(fmaxf(y1, 0.0f), mh);
    x2 = fminf(fmaxf(x2, 0.0f), mw);
    y2 = fminf(fmaxf(y2, 0.0f), mh);

    float ws = x2 - x1 + 1.0f;
    float hs = y2 - y1 + 1.0f;
    bool valid = (ws >= __fmul_rn(16.0f, sw)) && (hs >= __fmul_rn(16.0f, sh));

    unsigned int code = valid ? (0x3F800000u - __float_as_uint(p)) : INV30;

    int gi = b*N_ANCH + i;
    g_code [gi] = code;
    g_boxes[gi] = make_float4(x1, y1, x2, y2);
    atomicAdd(&g_hist[b*NBUCK + (code >> 18)], 1);
}

// ---------------- kernel 2: parallel cutoffs + hist re-zero + counter zero ----
// One 1024-thread CTA per batch; block scan of the 4096-bin histogram.
__global__ void __launch_bounds__(1024) cutoff_kernel()
{
    int b = blockIdx.x;
    int tid = threadIdx.x;                   // 1024 threads, 4 bins each
    __shared__ int ssum[1024];
    __shared__ int sCutA, sCutB;

    int hb = b*NBUCK + tid*4;
    int h0 = g_hist[hb+0], h1 = g_hist[hb+1], h2 = g_hist[hb+2], h3 = g_hist[hb+3];
    // re-zero for next replay (this kernel is the histogram's sole reader)
    g_hist[hb+0] = 0; g_hist[hb+1] = 0; g_hist[hb+2] = 0; g_hist[hb+3] = 0;

    int mysum = h0 + h1 + h2 + h3;
    ssum[tid] = mysum;
    __syncthreads();
    for (int off = 1; off < 1024; off <<= 1) {
        int v = (tid >= off) ? ssum[tid - off] : 0;
        __syncthreads();
        ssum[tid] += v;
        __syncthreads();
    }
    int incl = ssum[tid];
    int excl = incl - mysum;

    // exactly one thread satisfies each crossing (incl non-decreasing)
    if (excl < R1 && R1 <= incl) {
        int c = excl + h0, cut;
        if (c >= R1) cut = tid*4;
        else { c += h1; if (c >= R1) cut = tid*4 + 1;
               else { c += h2; if (c >= R1) cut = tid*4 + 2; else cut = tid*4 + 3; } }
        sCutA = cut;
    }
    if (excl < PRE && PRE <= incl) {
        int c = excl + h0, cut;
        if (c >= PRE) cut = tid*4;
        else { c += h1; if (c >= PRE) cut = tid*4 + 1;
               else { c += h2; if (c >= PRE) cut = tid*4 + 2; else cut = tid*4 + 3; } }
        sCutB = cut;
    }
    __syncthreads();
    if (tid == 0) { g_cutA[b] = sCutA; g_cutB[b] = sCutB; g_cnt[b] = 0; }
}

// ---------------- kernel 3: unordered warp-aggregated compaction --------------
// Order is irrelevant: key = (code<<16 | anchor_index) carries the exact
// (score, index) sort order, so any permutation ranks to the same sequence.
__global__ void compact_kernel()
{
    int blk = blockIdx.x, b = blockIdx.y;
    int tid = threadIdx.x;                  // 256 threads
    int lane = tid & 31;
    const unsigned FULL = 0xFFFFFFFFu;

    int i = blk*256 + tid;
    unsigned code = (i < N_ANCH) ? g_code[b*N_ANCH + i] : 0xFFFFFFFFu;
    int cutA = g_cutA[b];
    bool pred = (i < N_ANCH) && ((int)(code >> 18) <= cutA);
    unsigned mm = __ballot_sync(FULL, pred);
    int pre = __popc(mm & ((1u << lane) - 1u));
    int wbase = 0;
    if (lane == 0 && mm) wbase = atomicAdd(&g_cnt[b], __popc(mm));
    wbase = __shfl_sync(FULL, wbase, 0);
    if (pred) {
        int pos = wbase + pre;
        if (pos < CAPA)
            g_ckeys[b*CAPA + pos] = ((unsigned long long)code << 16) | (unsigned)i;
    }
}

// ---------------- kernel 4: rank-count "sort", 4 threads/item + fused gather --
// rank(key) = #{ keys < key }. Keys unique -> ranks = exact stable-sort
// positions. Sentinels never compare below a real key -> live prefix only.
__global__ void __launch_bounds__(RK_THR) rank_kernel()
{
    __shared__ __align__(16) unsigned long long sk[CAPA];   // 32 KB
    int cb = blockIdx.x;                      // item chunk, < RK_CTAS
    int b  = blockIdx.y;
    int tid = threadIdx.x;                    // RK_THR = 512
    const unsigned FULL = 0xFFFFFFFFu;

    int cnt = min(g_cnt[b], CAPA);
    int items0 = cb * (RK_THR/4);
    if (items0 >= cnt) return;                // whole chunk past live prefix

    int n2 = (cnt + 1) & ~1;                  // even upper bound <= CAPA
    for (int k2 = tid; k2 < n2; k2 += RK_THR)
        sk[k2] = g_ckeys[b*CAPA + k2];
    __syncthreads();

    int item = items0 + (tid >> 2);
    int q    = tid & 3;                       // quarter id
    bool live = (item < cnt);
    unsigned long long mykey = live ? sk[item] : 0ull;

    int r0 = 0, r1 = 0;
    if (live) {
        const ulonglong2* skv = reinterpret_cast<const ulonglong2*>(sk);
        int L = n2 >> 1;
        #pragma unroll 4
        for (int j = q; j < L; j += 4) {      // strided quarters; warp reads broadcast
            ulonglong2 v = skv[j];
            r0 += (v.x < mykey) ? 1 : 0;
            r1 += (v.y < mykey) ? 1 : 0;
        }
    }
    int r = r0 + r1;
    // combine the 4 partial ranks (lanes q=0..3 within each item group)
    r += __shfl_xor_sync(FULL, r, 1);
    r += __shfl_xor_sync(FULL, r, 2);

    if (live && q == 0 && r < R1) {
        unsigned code = (unsigned)((mykey >> 16) & 0x3FFFFFFFull);
        int idx = (int)(mykey & 0xFFFFull);
        float4 bx = g_boxes[b*N_ANCH + idx];
        float  ar = (bx.z - bx.x + 1.0f) * (bx.w - bx.y + 1.0f);
        g_sboxes[b*R1 + r] = bx;
        g_sarea [b*R1 + r] = ar;
        g_svalid[b*R1 + r] = (code != INV30) ? 1 : 0;
    }
}

// ---------------- shared IoU bit computation ----------------
__device__ __forceinline__ unsigned long long iou_bits(
    float4 bi, float ai, const float4* cbox, const float* carea, int jmax)
{
    unsigned long long bits = 0ull;
    #pragma unroll 8
    for (int k = 0; k < jmax; k++) {
        float4 bj = cbox[k];
        float xx1 = fmaxf(bi.x, bj.x);
        float yy1 = fmaxf(bi.y, bj.y);
        float xx2 = fminf(bi.z, bj.z);
        float yy2 = fminf(bi.w, bj.w);
        float iw = fmaxf(xx2 - xx1 + 1.0f, 0.0f);
        float ih = fmaxf(yy2 - yy1 + 1.0f, 0.0f);
        float inter = __fmul_rn(iw, ih);
        float sum   = __fadd_rn(ai, carea[k]);
        // exact prefilter: iou>0.7 requires inter>0.41*sum; 4*inter>=sum is a
        // safe necessary condition -> kept-bit set is bit-identical
        if (__fmul_rn(inter, 4.0f) >= sum) {
            float uni = __fsub_rn(sum, inter);
            float iou = __fdiv_rn(inter, uni);
            if (iou > NMS_THR) bits |= (1ull << k);
        }
    }
    return bits;
}

// ---------------- kernel 5: corner mask (top R1 x R1) ----------------
__global__ void mask1_kernel()
{
    int cb = blockIdx.x;                    // column word, < CH1
    int rt = blockIdx.y;                    // row 256-tile, < RT1
    int b  = blockIdx.z;
    int j0 = cb * 64;
    if (j0 + 63 < rt * MROWS) return;       // fully-lower tile: words stay 0

    __shared__ float4 cbox[64];
    __shared__ float  carea[64];
    int t = threadIdx.x;
    if (t < 64) {
        cbox[t]  = g_sboxes[b*R1 + j0 + t];
        carea[t] = g_sarea [b*R1 + j0 + t];
    }
    __syncthreads();

    int i = rt * MROWS + t;                 // < R1
    int d = i - j0;
    size_t word = ((size_t)(b*R1 + i))*CH1 + cb;
    if (d >= 63) { g_mask1[word] = 0ull; return; }

    unsigned long long bits = iou_bits(g_sboxes[b*R1 + i], g_sarea[b*R1 + i],
                                       cbox, carea, 64);
    if (d >= 0) bits &= (~0ull) << (d + 1);
    g_mask1[word] = bits;
}

// ---------------- kernel 6: corner scan + inline exact fallback ----------------
__global__ void __launch_bounds__(1024) scan1_fb_kernel(float* __restrict__ out)
{
    int b    = blockIdx.x;
    int tid  = threadIdx.x;                 // 1024 threads
    int lane = tid & 31;
    int warp = tid >> 5;
    const unsigned FULL = 0xFFFFFFFFu;

    __shared__ unsigned long long removed[CH1];
    __shared__ int keptList[POST];
    __shared__ int sDone;

    // ---- warp 0: greedy scan over the corner mask ----
    if (warp == 0) {
        if (lane < CH1) removed[lane] = 0ull;
        __syncwarp();

        int kept = 0;
        for (int c = 0; c < CH1 && kept < POST; c++) {
            int r0 = c * 64;
            int ra = r0 + lane, rb2 = r0 + 32 + lane;

            unsigned lo = __ballot_sync(FULL, g_svalid[b*R1 + ra ] != 0);
            unsigned hi = __ballot_sync(FULL, g_svalid[b*R1 + rb2] != 0);
            unsigned long long validm = (unsigned long long)lo | ((unsigned long long)hi << 32);

            unsigned long long m0 = g_mask1[((size_t)(b*R1 + ra ))*CH1 + c];
            unsigned long long m1 = g_mask1[((size_t)(b*R1 + rb2))*CH1 + c];

            unsigned long long cand = validm & ~removed[c];
            unsigned long long keptbits = 0ull;
            while (cand && kept < POST) {
                int l = __ffsll((long long)cand) - 1;
                keptList[kept] = r0 + l;
                kept++;
                keptbits |= (1ull << l);
                unsigned long long intra = (l < 32) ? __shfl_sync(FULL, m0, l)
                                                    : __shfl_sync(FULL, m1, l - 32);
                cand &= ~intra;
                cand &= ~(1ull << l);
            }

            if (keptbits) {
                unsigned long long acc = 0ull;       // lane -> word (CH1==32)
                unsigned long long kb2 = keptbits;
                while (kb2) {
                    int l = __ffsll((long long)kb2) - 1;
                    kb2 &= kb2 - 1;
                    acc |= g_mask1[((size_t)(b*R1 + r0 + l))*CH1 + lane];
                }
                removed[lane] |= acc;
            }
            __syncwarp();
        }
        if (lane == 0)
            sDone = (kept >= POST && g_cnt[b] <= CAPA) ? 1 : 0;
    }
    __syncthreads();

    if (sDone) {
        for (int r = tid; r < POST; r += 1024) {
            float* o = out + ((size_t)(b*POST + r))*5;
            float4 bx = g_sboxes[b*R1 + keptList[r]];
            o[0] = (float)b; o[1] = bx.x; o[2] = bx.y; o[3] = bx.z; o[4] = bx.w;
        }
        return;
    }

    // ================= exact fallback (not expected on real data) ============
    __shared__ int fCnt;
    if (tid == 0) fCnt = 0;
    __syncthreads();

    int cutB = g_cutB[b];
    for (int i0 = 0; i0 < NPAD; i0 += 1024) {
        int i = i0 + tid;
        unsigned code = (i < N_ANCH) ? g_code[b*N_ANCH + i] : 0xFFFFFFFFu;
        bool pred = (i < N_ANCH) && ((int)(code >> 18) <= cutB);
        unsigned mm = __ballot_sync(FULL, pred);
        int pre = __popc(mm & ((1u << lane) - 1u));
        int wbase = 0;
        if (lane == 0 && mm) wbase = atomicAdd(&fCnt, __popc(mm));
        wbase = __shfl_sync(FULL, wbase, 0);
        if (pred) {
            int pos = wbase + pre;
            if (pos < FCAP)
                g_fkeys[b*FCAP + pos] = ((unsigned long long)code << 16) | (unsigned)i;
        }
    }
    __syncthreads();
    int total = fCnt;
    for (int j = tid; j < FCAP; j += 1024)
        if (j >= total) g_fkeys[b*FCAP + j] = ~0ull;
    __syncthreads();

    // bitonic sort of FCAP keys in gmem (single CTA; perf irrelevant)
    unsigned long long* Ak = &g_fkeys[b*FCAP];
    for (int k = 2; k <= FCAP; k <<= 1) {
        for (int j = k >> 1; j > 0; j >>= 1) {
            for (int i = tid; i < FCAP; i += 1024) {
                int ixj = i ^ j;
                if (ixj > i) {
                    bool up = ((i & k) == 0);
                    unsigned long long a = Ak[i], c = Ak[ixj];
                    if ((a > c) == up) { Ak[i] = c; Ak[ixj] = a; }
                }
            }
            __syncthreads();
        }
    }

    // greedy NMS over sorted top-PRE with exact IoU semantics
    __shared__ float4 kbox[POST];
    __shared__ float  karea[POST];
    __shared__ int kcnt, supp;
    if (tid == 0) kcnt = 0;
    __syncthreads();

    for (int r = 0; r < PRE; r++) {
        if (kcnt >= POST) break;
        unsigned long long key = Ak[r];
        unsigned code = (unsigned)((key >> 16) & 0x3FFFFFFFull);
        if (code == INV30) break;           // sorted: rest invalid/sentinel
        int idx = (int)(key & 0xFFFFull);
        float4 bx = g_boxes[b*N_ANCH + idx];
        float ar = (bx.z - bx.x + 1.0f) * (bx.w - bx.y + 1.0f);
        if (tid == 0) supp = 0;
        __syncthreads();
        int kc = kcnt;
        for (int t = tid; t < kc; t += 1024) {
            float4 bj = kbox[t];
            float xx1 = fmaxf(bx.x, bj.x);
            float yy1 = fmaxf(bx.y, bj.y);
            float xx2 = fminf(bx.z, bj.z);
            float yy2 = fminf(bx.w, bj.w);
            float iw = fmaxf(xx2 - xx1 + 1.0f, 0.0f);
            float ih = fmaxf(yy2 - yy1 + 1.0f, 0.0f);
            float inter = __fmul_rn(iw, ih);
            float sum   = __fadd_rn(ar, karea[t]);
            if (__fmul_rn(inter, 4.0f) >= sum) {
                float uni = __fsub_rn(sum, inter);
                float iou = __fdiv_rn(inter, uni);
                if (iou > NMS_THR) supp = 1;
            }
        }
        __syncthreads();
        if (!supp && tid == 0) { kbox[kcnt] = bx; karea[kcnt] = ar; kcnt = kcnt + 1; }
        __syncthreads();
    }

    int kc = kcnt;
    for (int r = tid; r < POST; r += 1024) {
        float* o = out + ((size_t)(b*POST + r))*5;
        if (r < kc) {
            float4 bx = kbox[r];
            o[0] = (float)b; o[1] = bx.x; o[2] = bx.y; o[3] = bx.z; o[4] = bx.w;
        } else {
            o[0] = (float)b; o[1] = 0.0f; o[2] = 0.0f; o[3] = 0.0f; o[4] = 0.0f;
        }
    }
}

// ---------------- launch: 6 kernels ----------------
extern "C" void kernel_launch(void* const* d_in, const int* in_sizes, int n_in,
                              void* d_out, int out_size)
{
    const float* scores  = (const float*)d_in[0];
    const float* deltas  = (const float*)d_in[1];
    const float* anchors = (const float*)d_in[2];
    const float* iminfo  = (const float*)d_in[3];
    float* out = (float*)d_out;

    const int total = B_ * N_ANCH;
    prep_kernel<<<(total + 255) / 256, 256>>>(scores, deltas, anchors, iminfo);
    cutoff_kernel<<<B_, 1024>>>();
    compact_kernel<<<dim3(NBLK, B_), 256>>>();
    rank_kernel<<<dim3(RK_CTAS, B_), RK_THR>>>();

    dim3 m1grid(CH1, RT1, B_);
    mask1_kernel<<<m1grid, MROWS>>>();
    scan1_fb_kernel<<<B_, 1024>>>(out);
}

// round 16
// speedup vs baseline: 1.4112x; 1.2057x over previous
#include <cuda_runtime.h>
#include <cuda_bf16.h>
#include <cstdint>

// ---------------- problem constants ----------------
#define FH_   50
#define FW_   84
#define A_    12
#define B_    4
#define PIX   (FH_*FW_)        // 4200
#define N_ANCH (PIX*A_)        // 50400
#define PRE   6000
#define POST  300
#define NMS_THR 0.7f
#define NBUCK 4096
#define NBLK  197              // ceil(N_ANCH/256)
#define CAPA  4096             // fast-path compact capacity
#define FCAP  8192             // fallback compact capacity
#define INV30 0x3FFFFFFFu
// fast-path corner: top R1 rows x R1 cols (300 kept needs >=29% keep-rate)
#define R1    1024
#define CH1   16               // R1/64 column words
#define RT1   4                // R1/256 row tiles
#define MROWS 256
#define NPAD  51200            // N_ANCH rounded up to 1024
// rank kernel shape: 128 items per CTA, 4 threads per item
#define RK_CTAS 32             // CTAs per batch
#define RK_THR  512            // threads per CTA

static_assert(CH1*64 == R1 && RT1*MROWS == R1, "phase1 dims");
static_assert(NBLK*256 >= N_ANCH, "NBLK");
static_assert(N_ANCH < 65536, "index must fit in 16 bits");
static_assert(RK_CTAS*(RK_THR/4) == CAPA, "rank shape");
static_assert(CH1 <= 32, "scan lane guard assumes CH1<=32");

// Correctly-rounded float exp: short fp64 poly + Ziv check, rare libdevice
// fallback. Bit-identical to (float)exp((double)x) for every input.
__device__ __forceinline__ float exp_cr(float x) {
    double xd = (double)x;
    double t  = xd * 1.4426950408889634;
    int    k  = __double2int_rn(t);
    double kd = (double)k;
    double r  = __fma_rn(kd, -0.6931471805599453,    xd);
    r         = __fma_rn(kd, -2.3190468138462996e-17, r);
    double p = 2.505210838544172e-08;
    p = __fma_rn(p, r, 2.755731922398589e-07);
    p = __fma_rn(p, r, 2.7557319223985893e-06);
    p = __fma_rn(p, r, 2.48015873015873e-05);
    p = __fma_rn(p, r, 1.984126984126984e-04);
    p = __fma_rn(p, r, 1.3888888888888889e-03);
    p = __fma_rn(p, r, 8.333333333333333e-03);
    p = __fma_rn(p, r, 4.1666666666666664e-02);
    p = __fma_rn(p, r, 0.16666666666666666);
    p = __fma_rn(p, r, 0.5);
    p = __fma_rn(p, r, 1.0);
    p = __fma_rn(p, r, 1.0);
    double yd = p * __longlong_as_double((long long)(1023 + k) << 52);
    float flo = (float)(yd * (1.0 - 1.0e-12));
    float fhi = (float)(yd * (1.0 + 1.0e-12));
    if (flo == fhi) return flo;
    return (float)exp(xd);
}

// ---------------- static device scratch ----------------
__device__ float4             g_boxes[B_*N_ANCH];
__device__ unsigned int       g_code [B_*N_ANCH];
__device__ int                g_hist [B_*NBUCK];   // zero-init; re-zeroed by cutoff
__device__ int                g_cutA [B_];
__device__ int                g_cutB [B_];
__device__ int                g_cnt  [B_];         // compaction counter (zeroed by cutoff)
__device__ unsigned long long g_ckeys[B_*CAPA];    // sentinel-filled by prep
__device__ float4             g_sboxes[B_*R1];
__device__ float              g_sarea [B_*R1];
__device__ unsigned char      g_svalid[B_*R1];
// corner mask (zero-init; fully-lower words never written -> stay 0)
__device__ unsigned long long g_mask1[(size_t)B_*R1*CH1];
// fallback scratch (never touched on fast path)
__device__ unsigned long long g_fkeys[B_*FCAP];

// ---------------- kernel 1: softmax + decode + code + histogram + sentinel ----
__global__ void prep_kernel(const float* __restrict__ scores,
                            const float* __restrict__ deltas,
                            const float* __restrict__ anchors,
                            const float* __restrict__ iminfo)
{
    int idx = blockIdx.x * blockDim.x + threadIdx.x;
    if (idx >= B_*N_ANCH) return;

    // spare duty: sentinel-fill compact buffer for this replay
    if (idx < B_*CAPA) g_ckeys[idx] = ~0ull;

    int pix = idx % PIX;
    int ba  = idx / PIX;
    int b   = ba / A_;
    int a   = ba % A_;

    // softmax over (2a,2a+1): max-shift makes one exp exactly 1.0; single
    // E=exp(-|s1-s0|) reproduces the reference bitwise.
    const float* sp = scores + ((size_t)(b*2*A_ + 2*a))*PIX + pix;
    float s0 = sp[0];
    float s1 = sp[PIX];
    float dneg = (s1 >= s0) ? __fsub_rn(s0, s1) : __fsub_rn(s1, s0);
    float E     = exp_cr(dneg);
    float denom = __fadd_rn(E, 1.0f);
    float p = (s1 >= s0) ? __fdiv_rn(1.0f, denom) : __fdiv_rn(E, denom);

    const float* dp = deltas + ((size_t)(b*4*A_ + 4*a))*PIX + pix;
    float d0 = dp[0], d1 = dp[PIX], d2 = dp[2*PIX], d3 = dp[3*PIX];

    int i = pix*A_ + a;
    float4 an = reinterpret_cast<const float4*>(anchors)[i];

    float w  = an.z - an.x + 1.0f;
    float h  = an.w - an.y + 1.0f;
    float cx = __fadd_rn(an.x, __fmul_rn(0.5f, w));
    float cy = __fadd_rn(an.y, __fmul_rn(0.5f, h));
    float pcx = __fadd_rn(__fmul_rn(d0, w), cx);
    float pcy = __fadd_rn(__fmul_rn(d1, h), cy);
    float pw  = __fmul_rn(exp_cr(d2), w);
    float ph  = __fmul_rn(exp_cr(d3), h);
    float hx  = __fmul_rn(0.5f, pw);
    float hy  = __fmul_rn(0.5f, ph);
    float x1  = __fsub_rn(pcx, hx);
    float y1  = __fsub_rn(pcy, hy);
    float x2  = __fadd_rn(pcx, hx);
    float y2  = __fadd_rn(pcy, hy);

    float imh = iminfo[b*4+0], imw = iminfo[b*4+1];
    float sh  = iminfo[b*4+2], sw  = iminfo[b*4+3];
    float mw  = imw - 1.0f, mh = imh - 1.0f;
    x1 = fminf(fmaxf(x1, 0.0f), mw);
    y1 = fminf(fmaxf(y1, 0.0f), mh);
    x2 = fminf(fmaxf(x2, 0.0f), mw);
    y2 = fminf(fmaxf(y2, 0.0f), mh);

    float ws = x2 - x1 + 1.0f;
    float hs = y2 - y1 + 1.0f;
    bool valid = (ws >= __fmul_rn(16.0f, sw)) && (hs >= __fmul_rn(16.0f, sh));

    unsigned int code = valid ? (0x3F800000u - __float_as_uint(p)) : INV30;

    int gi = b*N_ANCH + i;
    g_code [gi] = code;
    g_boxes[gi] = make_float4(x1, y1, x2, y2);
    atomicAdd(&g_hist[b*NBUCK + (code >> 18)], 1);
}

// ---------------- kernel 2: parallel cutoffs + hist re-zero + counter zero ----
__global__ void __launch_bounds__(1024) cutoff_kernel()
{
    int b = blockIdx.x;
    int tid = threadIdx.x;                   // 1024 threads, 4 bins each
    __shared__ int ssum[1024];
    __shared__ int sCutA, sCutB;

    int hb = b*NBUCK + tid*4;
    int h0 = g_hist[hb+0], h1 = g_hist[hb+1], h2 = g_hist[hb+2], h3 = g_hist[hb+3];
    // re-zero for next replay (this kernel is the histogram's sole reader)
    g_hist[hb+0] = 0; g_hist[hb+1] = 0; g_hist[hb+2] = 0; g_hist[hb+3] = 0;

    int mysum = h0 + h1 + h2 + h3;
    ssum[tid] = mysum;
    __syncthreads();
    for (int off = 1; off < 1024; off <<= 1) {
        int v = (tid >= off) ? ssum[tid - off] : 0;
        __syncthreads();
        ssum[tid] += v;
        __syncthreads();
    }
    int incl = ssum[tid];
    int excl = incl - mysum;

    if (excl < R1 && R1 <= incl) {
        int c = excl + h0, cut;
        if (c >= R1) cut = tid*4;
        else { c += h1; if (c >= R1) cut = tid*4 + 1;
               else { c += h2; if (c >= R1) cut = tid*4 + 2; else cut = tid*4 + 3; } }
        sCutA = cut;
    }
    if (excl < PRE && PRE <= incl) {
        int c = excl + h0, cut;
        if (c >= PRE) cut = tid*4;
        else { c += h1; if (c >= PRE) cut = tid*4 + 1;
               else { c += h2; if (c >= PRE) cut = tid*4 + 2; else cut = tid*4 + 3; } }
        sCutB = cut;
    }
    __syncthreads();
    if (tid == 0) { g_cutA[b] = sCutA; g_cutB[b] = sCutB; g_cnt[b] = 0; }
}

// ---------------- kernel 3: unordered warp-aggregated compaction --------------
__global__ void compact_kernel()
{
    int blk = blockIdx.x, b = blockIdx.y;
    int tid = threadIdx.x;                  // 256 threads
    int lane = tid & 31;
    const unsigned FULL = 0xFFFFFFFFu;

    int i = blk*256 + tid;
    unsigned code = (i < N_ANCH) ? g_code[b*N_ANCH + i] : 0xFFFFFFFFu;
    int cutA = g_cutA[b];
    bool pred = (i < N_ANCH) && ((int)(code >> 18) <= cutA);
    unsigned mm = __ballot_sync(FULL, pred);
    int pre = __popc(mm & ((1u << lane) - 1u));
    int wbase = 0;
    if (lane == 0 && mm) wbase = atomicAdd(&g_cnt[b], __popc(mm));
    wbase = __shfl_sync(FULL, wbase, 0);
    if (pred) {
        int pos = wbase + pre;
        if (pos < CAPA)
            g_ckeys[b*CAPA + pos] = ((unsigned long long)code << 16) | (unsigned)i;
    }
}

// ---------------- kernel 4: rank-count "sort", 4 threads/item + fused gather --
__global__ void __launch_bounds__(RK_THR) rank_kernel()
{
    __shared__ __align__(16) unsigned long long sk[CAPA];   // 32 KB
    int cb = blockIdx.x;                      // item chunk, < RK_CTAS
    int b  = blockIdx.y;
    int tid = threadIdx.x;                    // RK_THR = 512
    const unsigned FULL = 0xFFFFFFFFu;

    int cnt = min(g_cnt[b], CAPA);
    int items0 = cb * (RK_THR/4);
    if (items0 >= cnt) return;                // whole chunk past live prefix

    int n2 = (cnt + 1) & ~1;                  // even upper bound <= CAPA
    for (int k2 = tid; k2 < n2; k2 += RK_THR)
        sk[k2] = g_ckeys[b*CAPA + k2];
    __syncthreads();

    int item = items0 + (tid >> 2);
    int q    = tid & 3;                       // quarter id
    bool live = (item < cnt);
    unsigned long long mykey = live ? sk[item] : 0ull;

    int r0 = 0, r1 = 0;
    if (live) {
        const ulonglong2* skv = reinterpret_cast<const ulonglong2*>(sk);
        int L = n2 >> 1;
        #pragma unroll 4
        for (int j = q; j < L; j += 4) {
            ulonglong2 v = skv[j];
            r0 += (v.x < mykey) ? 1 : 0;
            r1 += (v.y < mykey) ? 1 : 0;
        }
    }
    int r = r0 + r1;
    r += __shfl_xor_sync(FULL, r, 1);
    r += __shfl_xor_sync(FULL, r, 2);

    if (live && q == 0 && r < R1) {
        unsigned code = (unsigned)((mykey >> 16) & 0x3FFFFFFFull);
        int idx = (int)(mykey & 0xFFFFull);
        float4 bx = g_boxes[b*N_ANCH + idx];
        float  ar = (bx.z - bx.x + 1.0f) * (bx.w - bx.y + 1.0f);
        g_sboxes[b*R1 + r] = bx;
        g_sarea [b*R1 + r] = ar;
        g_svalid[b*R1 + r] = (code != INV30) ? 1 : 0;
    }
}

// ---------------- shared IoU bit computation ----------------
__device__ __forceinline__ unsigned long long iou_bits(
    float4 bi, float ai, const float4* cbox, const float* carea, int jmax)
{
    unsigned long long bits = 0ull;
    #pragma unroll 8
    for (int k = 0; k < jmax; k++) {
        float4 bj = cbox[k];
        float xx1 = fmaxf(bi.x, bj.x);
        float yy1 = fmaxf(bi.y, bj.y);
        float xx2 = fminf(bi.z, bj.z);
        float yy2 = fminf(bi.w, bj.w);
        float iw = fmaxf(xx2 - xx1 + 1.0f, 0.0f);
        float ih = fmaxf(yy2 - yy1 + 1.0f, 0.0f);
        float inter = __fmul_rn(iw, ih);
        float sum   = __fadd_rn(ai, carea[k]);
        // exact prefilter: iou>0.7 requires inter>0.41*sum; 4*inter>=sum is a
        // safe necessary condition -> kept-bit set is bit-identical
        if (__fmul_rn(inter, 4.0f) >= sum) {
            float uni = __fsub_rn(sum, inter);
            float iou = __fdiv_rn(inter, uni);
            if (iou > NMS_THR) bits |= (1ull << k);
        }
    }
    return bits;
}

// ---------------- kernel 5: corner mask (top R1 x R1) ----------------
__global__ void mask1_kernel()
{
    int cb = blockIdx.x;                    // column word, < CH1
    int rt = blockIdx.y;                    // row 256-tile, < RT1
    int b  = blockIdx.z;
    int j0 = cb * 64;
    if (j0 + 63 < rt * MROWS) return;       // fully-lower tile: words stay 0

    __shared__ float4 cbox[64];
    __shared__ float  carea[64];
    int t = threadIdx.x;
    if (t < 64) {
        cbox[t]  = g_sboxes[b*R1 + j0 + t];
        carea[t] = g_sarea [b*R1 + j0 + t];
    }
    __syncthreads();

    int i = rt * MROWS + t;                 // < R1
    int d = i - j0;
    size_t word = ((size_t)(b*R1 + i))*CH1 + cb;
    if (d >= 63) { g_mask1[word] = 0ull; return; }

    unsigned long long bits = iou_bits(g_sboxes[b*R1 + i], g_sarea[b*R1 + i],
                                       cbox, carea, 64);
    if (d >= 0) bits &= (~0ull) << (d + 1);
    g_mask1[word] = bits;
}

// ---------------- kernel 6: corner scan + inline exact fallback ----------------
__global__ void __launch_bounds__(1024) scan1_fb_kernel(float* __restrict__ out)
{
    int b    = blockIdx.x;
    int tid  = threadIdx.x;                 // 1024 threads
    int lane = tid & 31;
    int warp = tid >> 5;
    const unsigned FULL = 0xFFFFFFFFu;

    __shared__ unsigned long long removed[CH1];
    __shared__ int keptList[POST];
    __shared__ int sDone;

    // ---- warp 0: greedy scan over the corner mask ----
    if (warp == 0) {
        if (lane < CH1) removed[lane] = 0ull;
        __syncwarp();

        int kept = 0;
        for (int c = 0; c < CH1 && kept < POST; c++) {
            int r0 = c * 64;
            int ra = r0 + lane, rb2 = r0 + 32 + lane;

            unsigned lo = __ballot_sync(FULL, g_svalid[b*R1 + ra ] != 0);
            unsigned hi = __ballot_sync(FULL, g_svalid[b*R1 + rb2] != 0);
            unsigned long long validm = (unsigned long long)lo | ((unsigned long long)hi << 32);

            unsigned long long m0 = g_mask1[((size_t)(b*R1 + ra ))*CH1 + c];
            unsigned long long m1 = g_mask1[((size_t)(b*R1 + rb2))*CH1 + c];

            unsigned long long cand = validm & ~removed[c];
            unsigned long long keptbits = 0ull;
            while (cand && kept < POST) {
                int l = __ffsll((long long)cand) - 1;
                keptList[kept] = r0 + l;
                kept++;
                keptbits |= (1ull << l);
                unsigned long long intra = (l < 32) ? __shfl_sync(FULL, m0, l)
                                                    : __shfl_sync(FULL, m1, l - 32);
                cand &= ~intra;
                cand &= ~(1ull << l);
            }

            if (keptbits) {
                unsigned long long acc = 0ull;       // lane -> word, lanes < CH1
                unsigned long long kb2 = keptbits;
                while (kb2) {
                    int l = __ffsll((long long)kb2) - 1;
                    kb2 &= kb2 - 1;
                    if (lane < CH1)
                        acc |= g_mask1[((size_t)(b*R1 + r0 + l))*CH1 + lane];
                }
                if (lane < CH1) removed[lane] |= acc;
            }
            __syncwarp();
        }
        if (lane == 0)
            sDone = (kept >= POST && g_cnt[b] <= CAPA) ? 1 : 0;
    }
    __syncthreads();

    if (sDone) {
        for (int r = tid; r < POST; r += 1024) {
            float* o = out + ((size_t)(b*POST + r))*5;
            float4 bx = g_sboxes[b*R1 + keptList[r]];
            o[0] = (float)b; o[1] = bx.x; o[2] = bx.y; o[3] = bx.z; o[4] = bx.w;
        }
        return;
    }

    // ================= exact fallback (not expected on real data) ============
    __shared__ int fCnt;
    if (tid == 0) fCnt = 0;
    __syncthreads();

    int cutB = g_cutB[b];
    for (int i0 = 0; i0 < NPAD; i0 += 1024) {
        int i = i0 + tid;
        unsigned code = (i < N_ANCH) ? g_code[b*N_ANCH + i] : 0xFFFFFFFFu;
        bool pred = (i < N_ANCH) && ((int)(code >> 18) <= cutB);
        unsigned mm = __ballot_sync(FULL, pred);
        int pre = __popc(mm & ((1u << lane) - 1u));
        int wbase = 0;
        if (lane == 0 && mm) wbase = atomicAdd(&fCnt, __popc(mm));
        wbase = __shfl_sync(FULL, wbase, 0);
        if (pred) {
            int pos = wbase + pre;
            if (pos < FCAP)
                g_fkeys[b*FCAP + pos] = ((unsigned long long)code << 16) | (unsigned)i;
        }
    }
    __syncthreads();
    int total = fCnt;
    for (int j = tid; j < FCAP; j += 1024)
        if (j >= total) g_fkeys[b*FCAP + j] = ~0ull;
    __syncthreads();

    // bitonic sort of FCAP keys in gmem (single CTA; perf irrelevant)
    unsigned long long* Ak = &g_fkeys[b*FCAP];
    for (int k = 2; k <= FCAP; k <<= 1) {
        for (int j = k >> 1; j > 0; j >>= 1) {
            for (int i = tid; i < FCAP; i += 1024) {
                int ixj = i ^ j;
                if (ixj > i) {
                    bool up = ((i & k) == 0);
                    unsigned long long a = Ak[i], c = Ak[ixj];
                    if ((a > c) == up) { Ak[i] = c; Ak[ixj] = a; }
                }
            }
            __syncthreads();
        }
    }

    // greedy NMS over sorted top-PRE with exact IoU semantics
    __shared__ float4 kbox[POST];
    __shared__ float  karea[POST];
    __shared__ int kcnt, supp;
    if (tid == 0) kcnt = 0;
    __syncthreads();

    for (int r = 0; r < PRE; r++) {
        if (kcnt >= POST) break;
        unsigned long long key = Ak[r];
        unsigned code = (unsigned)((key >> 16) & 0x3FFFFFFFull);
        if (code == INV30) break;           // sorted: rest invalid/sentinel
        int idx = (int)(key & 0xFFFFull);
        float4 bx = g_boxes[b*N_ANCH + idx];
        float ar = (bx.z - bx.x + 1.0f) * (bx.w - bx.y + 1.0f);
        if (tid == 0) supp = 0;
        __syncthreads();
        int kc = kcnt;
        for (int t = tid; t < kc; t += 1024) {
            float4 bj = kbox[t];
            float xx1 = fmaxf(bx.x, bj.x);
            float yy1 = fmaxf(bx.y, bj.y);
            float xx2 = fminf(bx.z, bj.z);
            float yy2 = fminf(bx.w, bj.w);
            float iw = fmaxf(xx2 - xx1 + 1.0f, 0.0f);
            float ih = fmaxf(yy2 - yy1 + 1.0f, 0.0f);
            float inter = __fmul_rn(iw, ih);
            float sum   = __fadd_rn(ar, karea[t]);
            if (__fmul_rn(inter, 4.0f) >= sum) {
                float uni = __fsub_rn(sum, inter);
                float iou = __fdiv_rn(inter, uni);
                if (iou > NMS_THR) supp = 1;
            }
        }
        __syncthreads();
        if (!supp && tid == 0) { kbox[kcnt] = bx; karea[kcnt] = ar; kcnt = kcnt + 1; }
        __syncthreads();
    }

    int kc = kcnt;
    for (int r = tid; r < POST; r += 1024) {
        float* o = out + ((size_t)(b*POST + r))*5;
        if (r < kc) {
            float4 bx = kbox[r];
            o[0] = (float)b; o[1] = bx.x; o[2] = bx.y; o[3] = bx.z; o[4] = bx.w;
        } else {
            o[0] = (float)b; o[1] = 0.0f; o[2] = 0.0f; o[3] = 0.0f; o[4] = 0.0f;
        }
    }
}

// ---------------- launch: 6 kernels ----------------
extern "C" void kernel_launch(void* const* d_in, const int* in_sizes, int n_in,
                              void* d_out, int out_size)
{
    const float* scores  = (const float*)d_in[0];
    const float* deltas  = (const float*)d_in[1];
    const float* anchors = (const float*)d_in[2];
    const float* iminfo  = (const float*)d_in[3];
    float* out = (float*)d_out;

    const int total = B_ * N_ANCH;
    prep_kernel<<<(total + 255) / 256, 256>>>(scores, deltas, anchors, iminfo);
    cutoff_kernel<<<B_, 1024>>>();
    compact_kernel<<<dim3(NBLK, B_), 256>>>();
    rank_kernel<<<dim3(RK_CTAS, B_), RK_THR>>>();

    dim3 m1grid(CH1, RT1, B_);
    mask1_kernel<<<m1grid, MROWS>>>();
    scan1_fb_kernel<<<B_, 1024>>>(out);
}

// round 17
// speedup vs baseline: 1.4926x; 1.0577x over previous
#include <cuda_runtime.h>
#include <cuda_bf16.h>
#include <cstdint>

// ---------------- problem constants ----------------
#define FH_   50
#define FW_   84
#define A_    12
#define B_    4
#define PIX   (FH_*FW_)        // 4200
#define N_ANCH (PIX*A_)        // 50400
#define PRE   6000
#define POST  300
#define NMS_THR 0.7f
#define NBUCK 4096
#define NBLK  197              // ceil(N_ANCH/256)
#define CAPA  4096             // fast-path compact capacity
#define FCAP  8192             // fallback compact capacity
#define INV30 0x3FFFFFFFu
// fast-path corner: top R1 rows x R1 cols (300 kept needs >=58.6% keep-rate;
// observed ~84.5% on this workload; exact fallback guards the miss case)
#define R1    512
#define CH1   8                // R1/64 column words
#define RT1   2                // R1/256 row tiles
#define MROWS 256
#define NPAD  51200            // N_ANCH rounded up to 1024
// rank kernel shape: 128 items per CTA, 4 threads per item
#define RK_CTAS 32             // CTAs per batch
#define RK_THR  512            // threads per CTA

static_assert(CH1*64 == R1 && RT1*MROWS == R1, "phase1 dims");
static_assert(NBLK*256 >= N_ANCH, "NBLK");
static_assert(N_ANCH < 65536, "index must fit in 16 bits");
static_assert(RK_CTAS*(RK_THR/4) == CAPA, "rank shape");
static_assert(CH1 <= 32, "scan lane guard assumes CH1<=32");

// Correctly-rounded float exp: short fp64 poly + Ziv check, rare libdevice
// fallback. Bit-identical to (float)exp((double)x) for every input.
__device__ __forceinline__ float exp_cr(float x) {
    double xd = (double)x;
    double t  = xd * 1.4426950408889634;
    int    k  = __double2int_rn(t);
    double kd = (double)k;
    double r  = __fma_rn(kd, -0.6931471805599453,    xd);
    r         = __fma_rn(kd, -2.3190468138462996e-17, r);
    double p = 2.505210838544172e-08;
    p = __fma_rn(p, r, 2.755731922398589e-07);
    p = __fma_rn(p, r, 2.7557319223985893e-06);
    p = __fma_rn(p, r, 2.48015873015873e-05);
    p = __fma_rn(p, r, 1.984126984126984e-04);
    p = __fma_rn(p, r, 1.3888888888888889e-03);
    p = __fma_rn(p, r, 8.333333333333333e-03);
    p = __fma_rn(p, r, 4.1666666666666664e-02);
    p = __fma_rn(p, r, 0.16666666666666666);
    p = __fma_rn(p, r, 0.5);
    p = __fma_rn(p, r, 1.0);
    p = __fma_rn(p, r, 1.0);
    double yd = p * __longlong_as_double((long long)(1023 + k) << 52);
    float flo = (float)(yd * (1.0 - 1.0e-12));
    float fhi = (float)(yd * (1.0 + 1.0e-12));
    if (flo == fhi) return flo;
    return (float)exp(xd);
}

// ---------------- static device scratch ----------------
__device__ float4             g_boxes[B_*N_ANCH];
__device__ unsigned int       g_code [B_*N_ANCH];
__device__ int                g_hist [B_*NBUCK];   // zero-init; re-zeroed by cutoff
__device__ int                g_cutA [B_];
__device__ int                g_cutB [B_];
__device__ int                g_cnt  [B_];         // compaction counter (zeroed by cutoff)
__device__ unsigned long long g_ckeys[B_*CAPA];    // sentinel-filled by prep
__device__ float4             g_sboxes[B_*R1];
__device__ float              g_sarea [B_*R1];
__device__ unsigned char      g_svalid[B_*R1];
// corner mask (zero-init; fully-lower words never written -> stay 0)
__device__ unsigned long long g_mask1[(size_t)B_*R1*CH1];
// fallback scratch (never touched on fast path)
__device__ unsigned long long g_fkeys[B_*FCAP];

// ---------------- kernel 1: softmax + decode + code + histogram + sentinel ----
__global__ void prep_kernel(const float* __restrict__ scores,
                            const float* __restrict__ deltas,
                            const float* __restrict__ anchors,
                            const float* __restrict__ iminfo)
{
    int idx = blockIdx.x * blockDim.x + threadIdx.x;
    if (idx >= B_*N_ANCH) return;

    // spare duty: sentinel-fill compact buffer for this replay
    if (idx < B_*CAPA) g_ckeys[idx] = ~0ull;

    int pix = idx % PIX;
    int ba  = idx / PIX;
    int b   = ba / A_;
    int a   = ba % A_;

    // softmax over (2a,2a+1): max-shift makes one exp exactly 1.0; single
    // E=exp(-|s1-s0|) reproduces the reference bitwise.
    const float* sp = scores + ((size_t)(b*2*A_ + 2*a))*PIX + pix;
    float s0 = sp[0];
    float s1 = sp[PIX];
    float dneg = (s1 >= s0) ? __fsub_rn(s0, s1) : __fsub_rn(s1, s0);
    float E     = exp_cr(dneg);
    float denom = __fadd_rn(E, 1.0f);
    float p = (s1 >= s0) ? __fdiv_rn(1.0f, denom) : __fdiv_rn(E, denom);

    const float* dp = deltas + ((size_t)(b*4*A_ + 4*a))*PIX + pix;
    float d0 = dp[0], d1 = dp[PIX], d2 = dp[2*PIX], d3 = dp[3*PIX];

    int i = pix*A_ + a;
    float4 an = reinterpret_cast<const float4*>(anchors)[i];

    float w  = an.z - an.x + 1.0f;
    float h  = an.w - an.y + 1.0f;
    float cx = __fadd_rn(an.x, __fmul_rn(0.5f, w));
    float cy = __fadd_rn(an.y, __fmul_rn(0.5f, h));
    float pcx = __fadd_rn(__fmul_rn(d0, w), cx);
    float pcy = __fadd_rn(__fmul_rn(d1, h), cy);
    float pw  = __fmul_rn(exp_cr(d2), w);
    float ph  = __fmul_rn(exp_cr(d3), h);
    float hx  = __fmul_rn(0.5f, pw);
    float hy  = __fmul_rn(0.5f, ph);
    float x1  = __fsub_rn(pcx, hx);
    float y1  = __fsub_rn(pcy, hy);
    float x2  = __fadd_rn(pcx, hx);
    float y2  = __fadd_rn(pcy, hy);

    float imh = iminfo[b*4+0], imw = iminfo[b*4+1];
    float sh  = iminfo[b*4+2], sw  = iminfo[b*4+3];
    float mw  = imw - 1.0f, mh = imh - 1.0f;
    x1 = fminf(fmaxf(x1, 0.0f), mw);
    y1 = fminf(fmaxf(y1, 0.0f), mh);
    x2 = fminf(fmaxf(x2, 0.0f), mw);
    y2 = fminf(fmaxf(y2, 0.0f), mh);

    float ws = x2 - x1 + 1.0f;
    float hs = y2 - y1 + 1.0f;
    bool valid = (ws >= __fmul_rn(16.0f, sw)) && (hs >= __fmul_rn(16.0f, sh));

    unsigned int code = valid ? (0x3F800000u - __float_as_uint(p)) : INV30;

    int gi = b*N_ANCH + i;
    g_code [gi] = code;
    g_boxes[gi] = make_float4(x1, y1, x2, y2);
    atomicAdd(&g_hist[b*NBUCK + (code >> 18)], 1);
}

// ---------------- kernel 2: parallel cutoffs + hist re-zero + counter zero ----
__global__ void __launch_bounds__(1024) cutoff_kernel()
{
    int b = blockIdx.x;
    int tid = threadIdx.x;                   // 1024 threads, 4 bins each
    __shared__ int ssum[1024];
    __shared__ int sCutA, sCutB;

    int hb = b*NBUCK + tid*4;
    int h0 = g_hist[hb+0], h1 = g_hist[hb+1], h2 = g_hist[hb+2], h3 = g_hist[hb+3];
    // re-zero for next replay (this kernel is the histogram's sole reader)
    g_hist[hb+0] = 0; g_hist[hb+1] = 0; g_hist[hb+2] = 0; g_hist[hb+3] = 0;

    int mysum = h0 + h1 + h2 + h3;
    ssum[tid] = mysum;
    __syncthreads();
    for (int off = 1; off < 1024; off <<= 1) {
        int v = (tid >= off) ? ssum[tid - off] : 0;
        __syncthreads();
        ssum[tid] += v;
        __syncthreads();
    }
    int incl = ssum[tid];
    int excl = incl - mysum;

    if (excl < R1 && R1 <= incl) {
        int c = excl + h0, cut;
        if (c >= R1) cut = tid*4;
        else { c += h1; if (c >= R1) cut = tid*4 + 1;
               else { c += h2; if (c >= R1) cut = tid*4 + 2; else cut = tid*4 + 3; } }
        sCutA = cut;
    }
    if (excl < PRE && PRE <= incl) {
        int c = excl + h0, cut;
        if (c >= PRE) cut = tid*4;
        else { c += h1; if (c >= PRE) cut = tid*4 + 1;
               else { c += h2; if (c >= PRE) cut = tid*4 + 2; else cut = tid*4 + 3; } }
        sCutB = cut;
    }
    __syncthreads();
    if (tid == 0) { g_cutA[b] = sCutA; g_cutB[b] = sCutB; g_cnt[b] = 0; }
}

// ---------------- kernel 3: unordered warp-aggregated compaction --------------
__global__ void compact_kernel()
{
    int blk = blockIdx.x, b = blockIdx.y;
    int tid = threadIdx.x;                  // 256 threads
    int lane = tid & 31;
    const unsigned FULL = 0xFFFFFFFFu;

    int i = blk*256 + tid;
    unsigned code = (i < N_ANCH) ? g_code[b*N_ANCH + i] : 0xFFFFFFFFu;
    int cutA = g_cutA[b];
    bool pred = (i < N_ANCH) && ((int)(code >> 18) <= cutA);
    unsigned mm = __ballot_sync(FULL, pred);
    int pre = __popc(mm & ((1u << lane) - 1u));
    int wbase = 0;
    if (lane == 0 && mm) wbase = atomicAdd(&g_cnt[b], __popc(mm));
    wbase = __shfl_sync(FULL, wbase, 0);
    if (pred) {
        int pos = wbase + pre;
        if (pos < CAPA)
            g_ckeys[b*CAPA + pos] = ((unsigned long long)code << 16) | (unsigned)i;
    }
}

// ---------------- kernel 4: rank-count "sort", 4 threads/item + fused gather --
__global__ void __launch_bounds__(RK_THR) rank_kernel()
{
    __shared__ __align__(16) unsigned long long sk[CAPA];   // 32 KB
    int cb = blockIdx.x;                      // item chunk, < RK_CTAS
    int b  = blockIdx.y;
    int tid = threadIdx.x;                    // RK_THR = 512
    const unsigned FULL = 0xFFFFFFFFu;

    int cnt = min(g_cnt[b], CAPA);
    int items0 = cb * (RK_THR/4);
    if (items0 >= cnt) return;                // whole chunk past live prefix

    int n2 = (cnt + 1) & ~1;                  // even upper bound <= CAPA
    for (int k2 = tid; k2 < n2; k2 += RK_THR)
        sk[k2] = g_ckeys[b*CAPA + k2];
    __syncthreads();

    int item = items0 + (tid >> 2);
    int q    = tid & 3;                       // quarter id
    bool live = (item < cnt);
    unsigned long long mykey = live ? sk[item] : 0ull;

    int r0 = 0, r1 = 0;
    if (live) {
        const ulonglong2* skv = reinterpret_cast<const ulonglong2*>(sk);
        int L = n2 >> 1;
        #pragma unroll 4
        for (int j = q; j < L; j += 4) {
            ulonglong2 v = skv[j];
            r0 += (v.x < mykey) ? 1 : 0;
            r1 += (v.y < mykey) ? 1 : 0;
        }
    }
    int r = r0 + r1;
    r += __shfl_xor_sync(FULL, r, 1);
    r += __shfl_xor_sync(FULL, r, 2);

    if (live && q == 0 && r < R1) {
        unsigned code = (unsigned)((mykey >> 16) & 0x3FFFFFFFull);
        int idx = (int)(mykey & 0xFFFFull);
        float4 bx = g_boxes[b*N_ANCH + idx];
        float  ar = (bx.z - bx.x + 1.0f) * (bx.w - bx.y + 1.0f);
        g_sboxes[b*R1 + r] = bx;
        g_sarea [b*R1 + r] = ar;
        g_svalid[b*R1 + r] = (code != INV30) ? 1 : 0;
    }
}

// ---------------- shared IoU bit computation ----------------
__device__ __forceinline__ unsigned long long iou_bits(
    float4 bi, float ai, const float4* cbox, const float* carea, int jmax)
{
    unsigned long long bits = 0ull;
    #pragma unroll 8
    for (int k = 0; k < jmax; k++) {
        float4 bj = cbox[k];
        float xx1 = fmaxf(bi.x, bj.x);
        float yy1 = fmaxf(bi.y, bj.y);
        float xx2 = fminf(bi.z, bj.z);
        float yy2 = fminf(bi.w, bj.w);
        float iw = fmaxf(xx2 - xx1 + 1.0f, 0.0f);
        float ih = fmaxf(yy2 - yy1 + 1.0f, 0.0f);
        float inter = __fmul_rn(iw, ih);
        float sum   = __fadd_rn(ai, carea[k]);
        // exact prefilter: iou>0.7 requires inter>0.41*sum; 4*inter>=sum is a
        // safe necessary condition -> kept-bit set is bit-identical
        if (__fmul_rn(inter, 4.0f) >= sum) {
            float uni = __fsub_rn(sum, inter);
            float iou = __fdiv_rn(inter, uni);
            if (iou > NMS_THR) bits |= (1ull << k);
        }
    }
    return bits;
}

// ---------------- kernel 5: corner mask (top R1 x R1) ----------------
__global__ void mask1_kernel()
{
    int cb = blockIdx.x;                    // column word, < CH1
    int rt = blockIdx.y;                    // row 256-tile, < RT1
    int b  = blockIdx.z;
    int j0 = cb * 64;
    if (j0 + 63 < rt * MROWS) return;       // fully-lower tile: words stay 0

    __shared__ float4 cbox[64];
    __shared__ float  carea[64];
    int t = threadIdx.x;
    if (t < 64) {
        cbox[t]  = g_sboxes[b*R1 + j0 + t];
        carea[t] = g_sarea [b*R1 + j0 + t];
    }
    __syncthreads();

    int i = rt * MROWS + t;                 // < R1
    int d = i - j0;
    size_t word = ((size_t)(b*R1 + i))*CH1 + cb;
    if (d >= 63) { g_mask1[word] = 0ull; return; }

    unsigned long long bits = iou_bits(g_sboxes[b*R1 + i], g_sarea[b*R1 + i],
                                       cbox, carea, 64);
    if (d >= 0) bits &= (~0ull) << (d + 1);
    g_mask1[word] = bits;
}

// ---------------- kernel 6: corner scan + inline exact fallback ----------------
__global__ void __launch_bounds__(1024) scan1_fb_kernel(float* __restrict__ out)
{
    int b    = blockIdx.x;
    int tid  = threadIdx.x;                 // 1024 threads
    int lane = tid & 31;
    int warp = tid >> 5;
    const unsigned FULL = 0xFFFFFFFFu;

    __shared__ unsigned long long removed[CH1];
    __shared__ int keptList[POST];
    __shared__ int sDone;

    // ---- warp 0: greedy scan over the corner mask ----
    if (warp == 0) {
        if (lane < CH1) removed[lane] = 0ull;
        __syncwarp();

        int kept = 0;
        for (int c = 0; c < CH1 && kept < POST; c++) {
            int r0 = c * 64;
            int ra = r0 + lane, rb2 = r0 + 32 + lane;

            unsigned lo = __ballot_sync(FULL, g_svalid[b*R1 + ra ] != 0);
            unsigned hi = __ballot_sync(FULL, g_svalid[b*R1 + rb2] != 0);
            unsigned long long validm = (unsigned long long)lo | ((unsigned long long)hi << 32);

            unsigned long long m0 = g_mask1[((size_t)(b*R1 + ra ))*CH1 + c];
            unsigned long long m1 = g_mask1[((size_t)(b*R1 + rb2))*CH1 + c];

            unsigned long long cand = validm & ~removed[c];
            unsigned long long keptbits = 0ull;
            while (cand && kept < POST) {
                int l = __ffsll((long long)cand) - 1;
                keptList[kept] = r0 + l;
                kept++;
                keptbits |= (1ull << l);
                unsigned long long intra = (l < 32) ? __shfl_sync(FULL, m0, l)
                                                    : __shfl_sync(FULL, m1, l - 32);
                cand &= ~intra;
                cand &= ~(1ull << l);
            }

            if (keptbits) {
                unsigned long long acc = 0ull;       // lane -> word, lanes < CH1
                unsigned long long kb2 = keptbits;
                while (kb2) {
                    int l = __ffsll((long long)kb2) - 1;
                    kb2 &= kb2 - 1;
                    if (lane < CH1)
                        acc |= g_mask1[((size_t)(b*R1 + r0 + l))*CH1 + lane];
                }
                if (lane < CH1) removed[lane] |= acc;
            }
            __syncwarp();
        }
        if (lane == 0)
            sDone = (kept >= POST && g_cnt[b] <= CAPA) ? 1 : 0;
    }
    __syncthreads();

    if (sDone) {
        for (int r = tid; r < POST; r += 1024) {
            float* o = out + ((size_t)(b*POST + r))*5;
            float4 bx = g_sboxes[b*R1 + keptList[r]];
            o[0] = (float)b; o[1] = bx.x; o[2] = bx.y; o[3] = bx.z; o[4] = bx.w;
        }
        return;
    }

    // ================= exact fallback (not expected on real data) ============
    __shared__ int fCnt;
    if (tid == 0) fCnt = 0;
    __syncthreads();

    int cutB = g_cutB[b];
    for (int i0 = 0; i0 < NPAD; i0 += 1024) {
        int i = i0 + tid;
        unsigned code = (i < N_ANCH) ? g_code[b*N_ANCH + i] : 0xFFFFFFFFu;
        bool pred = (i < N_ANCH) && ((int)(code >> 18) <= cutB);
        unsigned mm = __ballot_sync(FULL, pred);
        int pre = __popc(mm & ((1u << lane) - 1u));
        int wbase = 0;
        if (lane == 0 && mm) wbase = atomicAdd(&fCnt, __popc(mm));
        wbase = __shfl_sync(FULL, wbase, 0);
        if (pred) {
            int pos = wbase + pre;
            if (pos < FCAP)
                g_fkeys[b*FCAP + pos] = ((unsigned long long)code << 16) | (unsigned)i;
        }
    }
    __syncthreads();
    int total = fCnt;
    for (int j = tid; j < FCAP; j += 1024)
        if (j >= total) g_fkeys[b*FCAP + j] = ~0ull;
    __syncthreads();

    // bitonic sort of FCAP keys in gmem (single CTA; perf irrelevant)
    unsigned long long* Ak = &g_fkeys[b*FCAP];
    for (int k = 2; k <= FCAP; k <<= 1) {
        for (int j = k >> 1; j > 0; j >>= 1) {
            for (int i = tid; i < FCAP; i += 1024) {
                int ixj = i ^ j;
                if (ixj > i) {
                    bool up = ((i & k) == 0);
                    unsigned long long a = Ak[i], c = Ak[ixj];
                    if ((a > c) == up) { Ak[i] = c; Ak[ixj] = a; }
                }
            }
            __syncthreads();
        }
    }

    // greedy NMS over sorted top-PRE with exact IoU semantics
    __shared__ float4 kbox[POST];
    __shared__ float  karea[POST];
    __shared__ int kcnt, supp;
    if (tid == 0) kcnt = 0;
    __syncthreads();

    for (int r = 0; r < PRE; r++) {
        if (kcnt >= POST) break;
        unsigned long long key = Ak[r];
        unsigned code = (unsigned)((key >> 16) & 0x3FFFFFFFull);
        if (code == INV30) break;           // sorted: rest invalid/sentinel
        int idx = (int)(key & 0xFFFFull);
        float4 bx = g_boxes[b*N_ANCH + idx];
        float ar = (bx.z - bx.x + 1.0f) * (bx.w - bx.y + 1.0f);
        if (tid == 0) supp = 0;
        __syncthreads();
        int kc = kcnt;
        for (int t = tid; t < kc; t += 1024) {
            float4 bj = kbox[t];
            float xx1 = fmaxf(bx.x, bj.x);
            float yy1 = fmaxf(bx.y, bj.y);
            float xx2 = fminf(bx.z, bj.z);
            float yy2 = fminf(bx.w, bj.w);
            float iw = fmaxf(xx2 - xx1 + 1.0f, 0.0f);
            float ih = fmaxf(yy2 - yy1 + 1.0f, 0.0f);
            float inter = __fmul_rn(iw, ih);
            float sum   = __fadd_rn(ar, karea[t]);
            if (__fmul_rn(inter, 4.0f) >= sum) {
                float uni = __fsub_rn(sum, inter);
                float iou = __fdiv_rn(inter, uni);
                if (iou > NMS_THR) supp = 1;
            }
        }
        __syncthreads();
        if (!supp && tid == 0) { kbox[kcnt] = bx; karea[kcnt] = ar; kcnt = kcnt + 1; }
        __syncthreads();
    }

    int kc = kcnt;
    for (int r = tid; r < POST; r += 1024) {
        float* o = out + ((size_t)(b*POST + r))*5;
        if (r < kc) {
            float4 bx = kbox[r];
            o[0] = (float)b; o[1] = bx.x; o[2] = bx.y; o[3] = bx.z; o[4] = bx.w;
        } else {
            o[0] = (float)b; o[1] = 0.0f; o[2] = 0.0f; o[3] = 0.0f; o[4] = 0.0f;
        }
    }
}

// ---------------- launch: 6 kernels ----------------
extern "C" void kernel_launch(void* const* d_in, const int* in_sizes, int n_in,
                              void* d_out, int out_size)
{
    const float* scores  = (const float*)d_in[0];
    const float* deltas  = (const float*)d_in[1];
    const float* anchors = (const float*)d_in[2];
    const float* iminfo  = (const float*)d_in[3];
    float* out = (float*)d_out;

    const int total = B_ * N_ANCH;
    prep_kernel<<<(total + 255) / 256, 256>>>(scores, deltas, anchors, iminfo);
    cutoff_kernel<<<B_, 1024>>>();
    compact_kernel<<<dim3(NBLK, B_), 256>>>();
    rank_kernel<<<dim3(RK_CTAS, B_), RK_THR>>>();

    dim3 m1grid(CH1, RT1, B_);
    mask1_kernel<<<m1grid, MROWS>>>();
    scan1_fb_kernel<<<B_, 1024>>>(out);
}